// round 1
// baseline (speedup 1.0000x reference)
#include <cuda_runtime.h>
#include <math.h>

// Problem constants
#define B_SZ 4
#define C_SZ 2048
#define E_SZ 1024
#define H_SZ 16
#define D_SZ 64
#define HD   (H_SZ * D_SZ)     // 1024
#define F3   (3 * HD)          // 3072
#define M_SZ (B_SZ * C_SZ)     // 8192

// Scratch (device globals: allocation-free per harness rules)
__device__ float g_qkv[(size_t)M_SZ * F3];    // (8192, 3072)
__device__ float g_attn[(size_t)M_SZ * HD];   // (8192, 1024) head-interleaved flat

// ---------------------------------------------------------------------------
// SGEMM: C[M,N] = A[M,K] * B[N,K]^T   (A row-major MxK, B row-major NxK)
// 128x128 tile, BK=8, 256 threads, 8x8 per thread.
// ---------------------------------------------------------------------------
__global__ __launch_bounds__(256) void sgemm_nt_kernel(
    const float* __restrict__ A, const float* __restrict__ B,
    float* __restrict__ C, int M, int N, int K)
{
    constexpr int BM = 128, BN = 128, BK = 8;
    __shared__ __align__(16) float As[BK][BM];
    __shared__ __align__(16) float Bs[BK][BN];

    const int tid = threadIdx.x;
    const int bm = blockIdx.y * BM;
    const int bn = blockIdx.x * BN;
    const int lr = tid >> 1;          // 0..127
    const int lc = (tid & 1) * 4;     // 0 or 4
    const int trow = (tid >> 4) * 8;  // 0..120
    const int tcol = (tid & 15) * 8;  // 0..120

    const float* Aptr = A + (size_t)(bm + lr) * K + lc;
    const float* Bptr = B + (size_t)(bn + lr) * K + lc;

    float acc[8][8];
    #pragma unroll
    for (int i = 0; i < 8; i++)
        #pragma unroll
        for (int j = 0; j < 8; j++) acc[i][j] = 0.f;

    for (int k0 = 0; k0 < K; k0 += BK) {
        float4 a = *(const float4*)(Aptr + k0);
        float4 b = *(const float4*)(Bptr + k0);
        As[lc + 0][lr] = a.x; As[lc + 1][lr] = a.y;
        As[lc + 2][lr] = a.z; As[lc + 3][lr] = a.w;
        Bs[lc + 0][lr] = b.x; Bs[lc + 1][lr] = b.y;
        Bs[lc + 2][lr] = b.z; Bs[lc + 3][lr] = b.w;
        __syncthreads();

        #pragma unroll
        for (int kk = 0; kk < BK; kk++) {
            float4 ra0 = *(const float4*)&As[kk][trow];
            float4 ra1 = *(const float4*)&As[kk][trow + 4];
            float4 rb0 = *(const float4*)&Bs[kk][tcol];
            float4 rb1 = *(const float4*)&Bs[kk][tcol + 4];
            float ra[8] = {ra0.x, ra0.y, ra0.z, ra0.w, ra1.x, ra1.y, ra1.z, ra1.w};
            float rb[8] = {rb0.x, rb0.y, rb0.z, rb0.w, rb1.x, rb1.y, rb1.z, rb1.w};
            #pragma unroll
            for (int i = 0; i < 8; i++)
                #pragma unroll
                for (int j = 0; j < 8; j++)
                    acc[i][j] += ra[i] * rb[j];
        }
        __syncthreads();
    }

    #pragma unroll
    for (int i = 0; i < 8; i++) {
        float4* crow = (float4*)(C + (size_t)(bm + trow + i) * N + bn + tcol);
        crow[0] = make_float4(acc[i][0], acc[i][1], acc[i][2], acc[i][3]);
        crow[1] = make_float4(acc[i][4], acc[i][5], acc[i][6], acc[i][7]);
    }
}

// ---------------------------------------------------------------------------
// Flash attention (causal), fp32. One block = 64 query rows of one (b,h).
// 256 threads as 16x16; each thread owns a 4(row)x4(col) microtile.
// Smem: Q tile, K tile (reused for P after S is computed), V tile.
// ---------------------------------------------------------------------------
#define SROW 68   // 64 + 4 pad floats; keeps 16B alignment, stride 68 mod 32 = 4

__global__ __launch_bounds__(256) void attn_kernel(
    const float* __restrict__ qkv, float* __restrict__ outf)
{
    extern __shared__ float smf[];
    float* Qs  = smf;                  // 64*SROW
    float* KPs = smf + 64 * SROW;      // K tile, later P tile
    float* Vs  = smf + 2 * 64 * SROW;  // V tile

    const int tid = threadIdx.x;
    const int qb  = blockIdx.x;            // query block (64 rows)
    const int bh  = blockIdx.y;
    const int b   = bh / H_SZ, h = bh % H_SZ;
    const int ty  = tid >> 4, tx = tid & 15;

    const float* qbase = qkv + (size_t)(b * C_SZ + qb * 64) * F3 + h * D_SZ;
    const float* kbase = qkv + (size_t)(b * C_SZ) * F3 + HD + h * D_SZ;
    const float* vbase = qkv + (size_t)(b * C_SZ) * F3 + 2 * HD + h * D_SZ;

    // load Q tile (64 x 64)
    for (int i = tid; i < 64 * 16; i += 256) {
        int r = i >> 4, c = (i & 15) * 4;
        *(float4*)&Qs[r * SROW + c] = *(const float4*)(qbase + (size_t)r * F3 + c);
    }

    float m_[4], l_[4], o_[4][4];
    #pragma unroll
    for (int i = 0; i < 4; i++) {
        m_[i] = -INFINITY; l_[i] = 0.f;
        #pragma unroll
        for (int j = 0; j < 4; j++) o_[i][j] = 0.f;
    }

    for (int kb = 0; kb <= qb; kb++) {
        // load K, V tiles for this kv block
        for (int i = tid; i < 64 * 16; i += 256) {
            int r = i >> 4, c = (i & 15) * 4;
            *(float4*)&KPs[r * SROW + c] =
                *(const float4*)(kbase + (size_t)(kb * 64 + r) * F3 + c);
            *(float4*)&Vs[r * SROW + c] =
                *(const float4*)(vbase + (size_t)(kb * 64 + r) * F3 + c);
        }
        __syncthreads();

        // S = Q K^T  (4x4 per thread)
        float s[4][4];
        #pragma unroll
        for (int i = 0; i < 4; i++)
            #pragma unroll
            for (int j = 0; j < 4; j++) s[i][j] = 0.f;

        #pragma unroll
        for (int d4 = 0; d4 < 16; d4++) {
            float4 qv[4], kv[4];
            #pragma unroll
            for (int i = 0; i < 4; i++)
                qv[i] = *(const float4*)&Qs[(ty * 4 + i) * SROW + d4 * 4];
            #pragma unroll
            for (int j = 0; j < 4; j++)
                kv[j] = *(const float4*)&KPs[(tx * 4 + j) * SROW + d4 * 4];
            #pragma unroll
            for (int i = 0; i < 4; i++)
                #pragma unroll
                for (int j = 0; j < 4; j++)
                    s[i][j] += qv[i].x * kv[j].x + qv[i].y * kv[j].y +
                               qv[i].z * kv[j].z + qv[i].w * kv[j].w;
        }

        // scale + causal mask (only diagonal block needs masking)
        const float sc = 0.125f;  // 1/sqrt(64)
        const bool diag = (kb == qb);
        #pragma unroll
        for (int i = 0; i < 4; i++) {
            int lrow = ty * 4 + i;
            #pragma unroll
            for (int j = 0; j < 4; j++) {
                float v = s[i][j] * sc;
                if (diag && (tx * 4 + j) > lrow) v = -INFINITY;
                s[i][j] = v;
            }
        }

        __syncthreads();  // all S reads of KPs done -> safe to overwrite with P

        // online softmax; write P into KPs
        #pragma unroll
        for (int i = 0; i < 4; i++) {
            float rm = fmaxf(fmaxf(s[i][0], s[i][1]), fmaxf(s[i][2], s[i][3]));
            #pragma unroll
            for (int off = 8; off; off >>= 1)
                rm = fmaxf(rm, __shfl_xor_sync(0xffffffffu, rm, off));
            float mi    = fmaxf(m_[i], rm);
            float alpha = __expf(m_[i] - mi);
            float p0 = __expf(s[i][0] - mi);
            float p1 = __expf(s[i][1] - mi);
            float p2 = __expf(s[i][2] - mi);
            float p3 = __expf(s[i][3] - mi);
            float rs = p0 + p1 + p2 + p3;
            #pragma unroll
            for (int off = 8; off; off >>= 1)
                rs += __shfl_xor_sync(0xffffffffu, rs, off);
            l_[i] = l_[i] * alpha + rs;
            m_[i] = mi;
            #pragma unroll
            for (int j = 0; j < 4; j++) o_[i][j] *= alpha;
            *(float4*)&KPs[(ty * 4 + i) * SROW + tx * 4] = make_float4(p0, p1, p2, p3);
        }
        __syncthreads();  // P visible to all

        // O += P @ V
        #pragma unroll
        for (int k4 = 0; k4 < 16; k4++) {
            float4 pr[4];
            #pragma unroll
            for (int i = 0; i < 4; i++)
                pr[i] = *(const float4*)&KPs[(ty * 4 + i) * SROW + k4 * 4];
            #pragma unroll
            for (int kk = 0; kk < 4; kk++) {
                float4 vv = *(const float4*)&Vs[(k4 * 4 + kk) * SROW + tx * 4];
                #pragma unroll
                for (int i = 0; i < 4; i++) {
                    float pk = (kk == 0) ? pr[i].x : (kk == 1) ? pr[i].y
                             : (kk == 2) ? pr[i].z : pr[i].w;
                    o_[i][0] += pk * vv.x;
                    o_[i][1] += pk * vv.y;
                    o_[i][2] += pk * vv.z;
                    o_[i][3] += pk * vv.w;
                }
            }
        }
        __syncthreads();  // KPs/Vs reads done before next iteration's loads
    }

    // normalize + write flat output (row-major (b*C+c, h*64+d))
    #pragma unroll
    for (int i = 0; i < 4; i++) {
        float inv = 1.f / l_[i];
        size_t row = (size_t)(b * C_SZ + qb * 64 + ty * 4 + i);
        *(float4*)(outf + row * HD + h * D_SZ + tx * 4) =
            make_float4(o_[i][0] * inv, o_[i][1] * inv, o_[i][2] * inv, o_[i][3] * inv);
    }
}

// ---------------------------------------------------------------------------
extern "C" void kernel_launch(void* const* d_in, const int* in_sizes, int n_in,
                              void* d_out, int out_size)
{
    const float* x     = (const float*)d_in[0];   // (4,2048,1024)
    const float* w_qkv = (const float*)d_in[1];   // (3072,1024)
    const float* w_out = (const float*)d_in[2];   // (1024,1024)
    float* out = (float*)d_out;

    float *qkv = nullptr, *attn = nullptr;
    cudaGetSymbolAddress((void**)&qkv, g_qkv);
    cudaGetSymbolAddress((void**)&attn, g_attn);

    // 1) QKV projection: (8192,1024) x (3072,1024)^T -> (8192,3072)
    {
        dim3 grid(F3 / 128, M_SZ / 128);
        sgemm_nt_kernel<<<grid, 256>>>(x, w_qkv, qkv, M_SZ, F3, E_SZ);
    }

    // 2) causal flash attention -> (8192,1024) flat
    {
        int smem = 3 * 64 * SROW * (int)sizeof(float);  // 52224 B
        cudaFuncSetAttribute(attn_kernel,
                             cudaFuncAttributeMaxDynamicSharedMemorySize, smem);
        dim3 grid(C_SZ / 64, B_SZ * H_SZ);
        attn_kernel<<<grid, 256, smem>>>(qkv, attn);
    }

    // 3) output projection: (8192,1024) x (1024,1024)^T -> (8192,1024)
    {
        dim3 grid(E_SZ / 128, M_SZ / 128);
        sgemm_nt_kernel<<<grid, 256>>>(attn, w_out, out, M_SZ, E_SZ, HD);
    }
}

// round 4
// speedup vs baseline: 1.3551x; 1.3551x over previous
#include <cuda_runtime.h>
#include <cuda_bf16.h>
#include <math.h>
#include <cstdint>

// Problem constants
#define B_SZ 4
#define C_SZ 2048
#define E_SZ 1024
#define H_SZ 16
#define D_SZ 64
#define HD   (H_SZ * D_SZ)     // 1024
#define F3   (3 * HD)          // 3072
#define M_SZ (B_SZ * C_SZ)     // 8192

// Scratch
__device__ float g_qkv[(size_t)M_SZ * F3];    // (8192, 3072)
__device__ float g_attn[(size_t)M_SZ * HD];   // (8192, 1024)

// ---------------------------------------------------------------------------
// m16n8k16 bf16 mma (sm_80+ baseline PTX; valid on plain sm_103 target)
// ---------------------------------------------------------------------------
__device__ __forceinline__ void mma_bf16(float* c, const uint32_t* a, const uint32_t* b) {
    asm volatile(
        "mma.sync.aligned.m16n8k16.row.col.f32.bf16.bf16.f32 "
        "{%0,%1,%2,%3}, {%4,%5,%6,%7}, {%8,%9}, {%0,%1,%2,%3};"
        : "+f"(c[0]), "+f"(c[1]), "+f"(c[2]), "+f"(c[3])
        : "r"(a[0]), "r"(a[1]), "r"(a[2]), "r"(a[3]), "r"(b[0]), "r"(b[1]));
}

__device__ __forceinline__ uint32_t pack_bf16(__nv_bfloat16 a, __nv_bfloat16 b) {
    uint32_t r;
    uint16_t lo = __bfloat16_as_ushort(a), hi = __bfloat16_as_ushort(b);
    r = ((uint32_t)hi << 16) | lo;
    return r;
}

// ---------------------------------------------------------------------------
// split-bf16 GEMM: C[M,N] = A[M,K] * B[N,K]^T  (fp32 in/out, 3-term bf16)
// BM=BN=128, BK=32, 256 threads (8 warps: 4m x 2n), double-buffered smem.
// Smem: per buffer, Ahi/Alo/Bhi/Blo each 128 rows x 40 bf16 (stride 40).
// ---------------------------------------------------------------------------
#define BK 32
#define SSTB 40                     // smem row stride in bf16
#define OP_SZ (128 * SSTB)          // one operand array, bf16 units (5120)
#define BUF_SZ (4 * OP_SZ)          // Ahi,Alo,Bhi,Blo (20480 bf16 = 40960 B)
#define GEMM_SMEM (2 * BUF_SZ * 2)  // bytes: 81920

__global__ __launch_bounds__(256) void gemm_bf16x3_kernel(
    const float* __restrict__ A, const float* __restrict__ B,
    float* __restrict__ Cc, int M, int N, int K)
{
    extern __shared__ __nv_bfloat16 sm[];

    const int tid  = threadIdx.x;
    const int wid  = tid >> 5, lane = tid & 31;
    const int bm   = blockIdx.y * 128, bn = blockIdx.x * 128;
    const int wm   = (wid & 3) * 32;      // warp row offset
    const int wn   = (wid >> 2) * 64;     // warp col offset
    const int qr   = lane >> 2;           // 0..7
    const int qk   = lane & 3;            // 0..3

    // global load mapping: 128x32 fp32 per operand tile; 4 float4 per thread
    const int grow = tid >> 3;            // 0..31 (base row, +32*j)
    const int gq   = tid & 7;             // float4 index within row

    const float* Ag = A + (size_t)(bm + grow) * K + gq * 4;
    const float* Bg = B + (size_t)(bn + grow) * K + gq * 4;

    float acc[2][8][4];
    #pragma unroll
    for (int mt = 0; mt < 2; mt++)
        #pragma unroll
        for (int nt = 0; nt < 8; nt++)
            #pragma unroll
            for (int v = 0; v < 4; v++) acc[mt][nt][v] = 0.f;

    const int NT = K / BK;
    float4 aReg[4], bReg[4];

    // prefetch tile 0 into registers
    #pragma unroll
    for (int j = 0; j < 4; j++) {
        aReg[j] = *(const float4*)(Ag + (size_t)(32 * j) * K);
        bReg[j] = *(const float4*)(Bg + (size_t)(32 * j) * K);
    }

    for (int kt = 0; kt < NT; kt++) {
        const int buf = kt & 1;
        __nv_bfloat16* Ahi = sm + buf * BUF_SZ;
        __nv_bfloat16* Alo = Ahi + OP_SZ;
        __nv_bfloat16* Bhi = Alo + OP_SZ;
        __nv_bfloat16* Blo = Bhi + OP_SZ;

        // convert staged registers -> hi/lo bf16 smem
        #pragma unroll
        for (int j = 0; j < 4; j++) {
            const int row = grow + 32 * j;
            const int idx = row * SSTB + gq * 4;
            float av[4] = {aReg[j].x, aReg[j].y, aReg[j].z, aReg[j].w};
            float bv[4] = {bReg[j].x, bReg[j].y, bReg[j].z, bReg[j].w};
            __nv_bfloat16 ah[4], al[4], bh[4], bl[4];
            #pragma unroll
            for (int v = 0; v < 4; v++) {
                ah[v] = __float2bfloat16(av[v]);
                al[v] = __float2bfloat16(av[v] - __bfloat162float(ah[v]));
                bh[v] = __float2bfloat16(bv[v]);
                bl[v] = __float2bfloat16(bv[v] - __bfloat162float(bh[v]));
            }
            *(uint2*)&Ahi[idx] = make_uint2(pack_bf16(ah[0], ah[1]), pack_bf16(ah[2], ah[3]));
            *(uint2*)&Alo[idx] = make_uint2(pack_bf16(al[0], al[1]), pack_bf16(al[2], al[3]));
            *(uint2*)&Bhi[idx] = make_uint2(pack_bf16(bh[0], bh[1]), pack_bf16(bh[2], bh[3]));
            *(uint2*)&Blo[idx] = make_uint2(pack_bf16(bl[0], bl[1]), pack_bf16(bl[2], bl[3]));
        }
        __syncthreads();

        // prefetch next tile into registers (hide LDG under compute)
        if (kt + 1 < NT) {
            const int off = (kt + 1) * BK;
            #pragma unroll
            for (int j = 0; j < 4; j++) {
                aReg[j] = *(const float4*)(Ag + (size_t)(32 * j) * K + off);
                bReg[j] = *(const float4*)(Bg + (size_t)(32 * j) * K + off);
            }
        }

        // compute: 2 k16-steps
        #pragma unroll
        for (int ks = 0; ks < 2; ks++) {
            const int k0 = ks * 16;
            uint32_t afh[2][4], afl[2][4];
            #pragma unroll
            for (int mt = 0; mt < 2; mt++) {
                const int r0 = (wm + mt * 16 + qr) * SSTB;
                const int r1 = r0 + 8 * SSTB;
                afh[mt][0] = *(const uint32_t*)&Ahi[r0 + k0 + 2 * qk];
                afh[mt][1] = *(const uint32_t*)&Ahi[r1 + k0 + 2 * qk];
                afh[mt][2] = *(const uint32_t*)&Ahi[r0 + k0 + 8 + 2 * qk];
                afh[mt][3] = *(const uint32_t*)&Ahi[r1 + k0 + 8 + 2 * qk];
                afl[mt][0] = *(const uint32_t*)&Alo[r0 + k0 + 2 * qk];
                afl[mt][1] = *(const uint32_t*)&Alo[r1 + k0 + 2 * qk];
                afl[mt][2] = *(const uint32_t*)&Alo[r0 + k0 + 8 + 2 * qk];
                afl[mt][3] = *(const uint32_t*)&Alo[r1 + k0 + 8 + 2 * qk];
            }
            #pragma unroll
            for (int nt = 0; nt < 8; nt++) {
                const int nrow = (wn + nt * 8 + qr) * SSTB;
                uint32_t bfh[2], bfl[2];
                bfh[0] = *(const uint32_t*)&Bhi[nrow + k0 + 2 * qk];
                bfh[1] = *(const uint32_t*)&Bhi[nrow + k0 + 8 + 2 * qk];
                bfl[0] = *(const uint32_t*)&Blo[nrow + k0 + 2 * qk];
                bfl[1] = *(const uint32_t*)&Blo[nrow + k0 + 8 + 2 * qk];
                #pragma unroll
                for (int mt = 0; mt < 2; mt++) {
                    mma_bf16(acc[mt][nt], afh[mt], bfh);   // hi*hi
                    mma_bf16(acc[mt][nt], afh[mt], bfl);   // hi*lo
                    mma_bf16(acc[mt][nt], afl[mt], bfh);   // lo*hi
                }
            }
        }
        __syncthreads();
    }

    // epilogue
    #pragma unroll
    for (int mt = 0; mt < 2; mt++) {
        const int r = bm + wm + mt * 16 + qr;
        #pragma unroll
        for (int nt = 0; nt < 8; nt++) {
            const int ncol = bn + wn + nt * 8 + 2 * qk;
            *(float2*)(Cc + (size_t)r * N + ncol) =
                make_float2(acc[mt][nt][0], acc[mt][nt][1]);
            *(float2*)(Cc + (size_t)(r + 8) * N + ncol) =
                make_float2(acc[mt][nt][2], acc[mt][nt][3]);
        }
    }
}

// ---------------------------------------------------------------------------
// Flash attention (causal), fp32 SIMT (unchanged, known-correct)
// ---------------------------------------------------------------------------
#define SROW 68

__global__ __launch_bounds__(256) void attn_kernel(
    const float* __restrict__ qkv, float* __restrict__ outf)
{
    extern __shared__ float smf[];
    float* Qs  = smf;
    float* KPs = smf + 64 * SROW;
    float* Vs  = smf + 2 * 64 * SROW;

    const int tid = threadIdx.x;
    const int qb  = blockIdx.x;
    const int bh  = blockIdx.y;
    const int b   = bh / H_SZ, h = bh % H_SZ;
    const int ty  = tid >> 4, tx = tid & 15;

    const float* qbase = qkv + (size_t)(b * C_SZ + qb * 64) * F3 + h * D_SZ;
    const float* kbase = qkv + (size_t)(b * C_SZ) * F3 + HD + h * D_SZ;
    const float* vbase = qkv + (size_t)(b * C_SZ) * F3 + 2 * HD + h * D_SZ;

    for (int i = tid; i < 64 * 16; i += 256) {
        int r = i >> 4, c = (i & 15) * 4;
        *(float4*)&Qs[r * SROW + c] = *(const float4*)(qbase + (size_t)r * F3 + c);
    }

    float m_[4], l_[4], o_[4][4];
    #pragma unroll
    for (int i = 0; i < 4; i++) {
        m_[i] = -INFINITY; l_[i] = 0.f;
        #pragma unroll
        for (int j = 0; j < 4; j++) o_[i][j] = 0.f;
    }

    for (int kb = 0; kb <= qb; kb++) {
        for (int i = tid; i < 64 * 16; i += 256) {
            int r = i >> 4, c = (i & 15) * 4;
            *(float4*)&KPs[r * SROW + c] =
                *(const float4*)(kbase + (size_t)(kb * 64 + r) * F3 + c);
            *(float4*)&Vs[r * SROW + c] =
                *(const float4*)(vbase + (size_t)(kb * 64 + r) * F3 + c);
        }
        __syncthreads();

        float s[4][4];
        #pragma unroll
        for (int i = 0; i < 4; i++)
            #pragma unroll
            for (int j = 0; j < 4; j++) s[i][j] = 0.f;

        #pragma unroll
        for (int d4 = 0; d4 < 16; d4++) {
            float4 qv[4], kv[4];
            #pragma unroll
            for (int i = 0; i < 4; i++)
                qv[i] = *(const float4*)&Qs[(ty * 4 + i) * SROW + d4 * 4];
            #pragma unroll
            for (int j = 0; j < 4; j++)
                kv[j] = *(const float4*)&KPs[(tx * 4 + j) * SROW + d4 * 4];
            #pragma unroll
            for (int i = 0; i < 4; i++)
                #pragma unroll
                for (int j = 0; j < 4; j++)
                    s[i][j] += qv[i].x * kv[j].x + qv[i].y * kv[j].y +
                               qv[i].z * kv[j].z + qv[i].w * kv[j].w;
        }

        const float sc = 0.125f;
        const bool diag = (kb == qb);
        #pragma unroll
        for (int i = 0; i < 4; i++) {
            int lrow = ty * 4 + i;
            #pragma unroll
            for (int j = 0; j < 4; j++) {
                float v = s[i][j] * sc;
                if (diag && (tx * 4 + j) > lrow) v = -INFINITY;
                s[i][j] = v;
            }
        }

        __syncthreads();

        #pragma unroll
        for (int i = 0; i < 4; i++) {
            float rm = fmaxf(fmaxf(s[i][0], s[i][1]), fmaxf(s[i][2], s[i][3]));
            #pragma unroll
            for (int off = 8; off; off >>= 1)
                rm = fmaxf(rm, __shfl_xor_sync(0xffffffffu, rm, off));
            float mi    = fmaxf(m_[i], rm);
            float alpha = __expf(m_[i] - mi);
            float p0 = __expf(s[i][0] - mi);
            float p1 = __expf(s[i][1] - mi);
            float p2 = __expf(s[i][2] - mi);
            float p3 = __expf(s[i][3] - mi);
            float rs = p0 + p1 + p2 + p3;
            #pragma unroll
            for (int off = 8; off; off >>= 1)
                rs += __shfl_xor_sync(0xffffffffu, rs, off);
            l_[i] = l_[i] * alpha + rs;
            m_[i] = mi;
            #pragma unroll
            for (int j = 0; j < 4; j++) o_[i][j] *= alpha;
            *(float4*)&KPs[(ty * 4 + i) * SROW + tx * 4] = make_float4(p0, p1, p2, p3);
        }
        __syncthreads();

        #pragma unroll
        for (int k4 = 0; k4 < 16; k4++) {
            float4 pr[4];
            #pragma unroll
            for (int i = 0; i < 4; i++)
                pr[i] = *(const float4*)&KPs[(ty * 4 + i) * SROW + k4 * 4];
            #pragma unroll
            for (int kk = 0; kk < 4; kk++) {
                float4 vv = *(const float4*)&Vs[(k4 * 4 + kk) * SROW + tx * 4];
                #pragma unroll
                for (int i = 0; i < 4; i++) {
                    float pk = (kk == 0) ? pr[i].x : (kk == 1) ? pr[i].y
                             : (kk == 2) ? pr[i].z : pr[i].w;
                    o_[i][0] += pk * vv.x;
                    o_[i][1] += pk * vv.y;
                    o_[i][2] += pk * vv.z;
                    o_[i][3] += pk * vv.w;
                }
            }
        }
        __syncthreads();
    }

    #pragma unroll
    for (int i = 0; i < 4; i++) {
        float inv = 1.f / l_[i];
        size_t row = (size_t)(b * C_SZ + qb * 64 + ty * 4 + i);
        *(float4*)(outf + row * HD + h * D_SZ + tx * 4) =
            make_float4(o_[i][0] * inv, o_[i][1] * inv, o_[i][2] * inv, o_[i][3] * inv);
    }
}

// ---------------------------------------------------------------------------
extern "C" void kernel_launch(void* const* d_in, const int* in_sizes, int n_in,
                              void* d_out, int out_size)
{
    const float* x     = (const float*)d_in[0];   // (4,2048,1024)
    const float* w_qkv = (const float*)d_in[1];   // (3072,1024)
    const float* w_out = (const float*)d_in[2];   // (1024,1024)
    float* out = (float*)d_out;

    float *qkv = nullptr, *attn = nullptr;
    cudaGetSymbolAddress((void**)&qkv, g_qkv);
    cudaGetSymbolAddress((void**)&attn, g_attn);

    cudaFuncSetAttribute(gemm_bf16x3_kernel,
                         cudaFuncAttributeMaxDynamicSharedMemorySize, GEMM_SMEM);

    // 1) QKV projection: (8192,1024) x (3072,1024)^T -> (8192,3072)
    {
        dim3 grid(F3 / 128, M_SZ / 128);
        gemm_bf16x3_kernel<<<grid, 256, GEMM_SMEM>>>(x, w_qkv, qkv, M_SZ, F3, E_SZ);
    }

    // 2) causal flash attention -> (8192,1024) flat
    {
        int smem = 3 * 64 * SROW * (int)sizeof(float);
        cudaFuncSetAttribute(attn_kernel,
                             cudaFuncAttributeMaxDynamicSharedMemorySize, smem);
        dim3 grid(C_SZ / 64, B_SZ * H_SZ);
        attn_kernel<<<grid, 256, smem>>>(qkv, attn);
    }

    // 3) output projection: (8192,1024) x (1024,1024)^T -> (8192,1024)
    {
        dim3 grid(E_SZ / 128, M_SZ / 128);
        gemm_bf16x3_kernel<<<grid, 256, GEMM_SMEM>>>(attn, w_out, out, M_SZ, E_SZ, HD);
    }
}

// round 5
// speedup vs baseline: 2.6159x; 1.9303x over previous
#include <cuda_runtime.h>
#include <cuda_bf16.h>
#include <math.h>
#include <cstdint>

// Problem constants
#define B_SZ 4
#define C_SZ 2048
#define E_SZ 1024
#define H_SZ 16
#define D_SZ 64
#define HD   (H_SZ * D_SZ)     // 1024
#define F3   (3 * HD)          // 3072
#define M_SZ (B_SZ * C_SZ)     // 8192

// Scratch
__device__ float g_qkv[(size_t)M_SZ * F3];    // (8192, 3072)
__device__ float g_attn[(size_t)M_SZ * HD];   // (8192, 1024)

// ---------------------------------------------------------------------------
// m16n8k16 bf16 mma
// ---------------------------------------------------------------------------
__device__ __forceinline__ void mma_bf16(float* c, const uint32_t* a, const uint32_t* b) {
    asm volatile(
        "mma.sync.aligned.m16n8k16.row.col.f32.bf16.bf16.f32 "
        "{%0,%1,%2,%3}, {%4,%5,%6,%7}, {%8,%9}, {%0,%1,%2,%3};"
        : "+f"(c[0]), "+f"(c[1]), "+f"(c[2]), "+f"(c[3])
        : "r"(a[0]), "r"(a[1]), "r"(a[2]), "r"(a[3]), "r"(b[0]), "r"(b[1]));
}

__device__ __forceinline__ uint32_t pack_bf16(__nv_bfloat16 a, __nv_bfloat16 b) {
    uint16_t lo = __bfloat16_as_ushort(a), hi = __bfloat16_as_ushort(b);
    return ((uint32_t)hi << 16) | lo;
}

__device__ __forceinline__ void split2(float x, float y, uint32_t& hi, uint32_t& lo) {
    __nv_bfloat16 hx = __float2bfloat16(x), hy = __float2bfloat16(y);
    __nv_bfloat16 lx = __float2bfloat16(x - __bfloat162float(hx));
    __nv_bfloat16 ly = __float2bfloat16(y - __bfloat162float(hy));
    hi = pack_bf16(hx, hy);
    lo = pack_bf16(lx, ly);
}

// ---------------------------------------------------------------------------
// split-bf16 GEMM (unchanged from R4): C[M,N] = A[M,K]*B[N,K]^T
// ---------------------------------------------------------------------------
#define BK 32
#define SSTB 40
#define OP_SZ (128 * SSTB)
#define BUF_SZ (4 * OP_SZ)
#define GEMM_SMEM (2 * BUF_SZ * 2)

__global__ __launch_bounds__(256) void gemm_bf16x3_kernel(
    const float* __restrict__ A, const float* __restrict__ B,
    float* __restrict__ Cc, int M, int N, int K)
{
    extern __shared__ __nv_bfloat16 sm[];

    const int tid  = threadIdx.x;
    const int wid  = tid >> 5, lane = tid & 31;
    const int bm   = blockIdx.y * 128, bn = blockIdx.x * 128;
    const int wm   = (wid & 3) * 32;
    const int wn   = (wid >> 2) * 64;
    const int qr   = lane >> 2;
    const int qk   = lane & 3;

    const int grow = tid >> 3;
    const int gq   = tid & 7;

    const float* Ag = A + (size_t)(bm + grow) * K + gq * 4;
    const float* Bg = B + (size_t)(bn + grow) * K + gq * 4;

    float acc[2][8][4];
    #pragma unroll
    for (int mt = 0; mt < 2; mt++)
        #pragma unroll
        for (int nt = 0; nt < 8; nt++)
            #pragma unroll
            for (int v = 0; v < 4; v++) acc[mt][nt][v] = 0.f;

    const int NT = K / BK;
    float4 aReg[4], bReg[4];

    #pragma unroll
    for (int j = 0; j < 4; j++) {
        aReg[j] = *(const float4*)(Ag + (size_t)(32 * j) * K);
        bReg[j] = *(const float4*)(Bg + (size_t)(32 * j) * K);
    }

    for (int kt = 0; kt < NT; kt++) {
        const int buf = kt & 1;
        __nv_bfloat16* Ahi = sm + buf * BUF_SZ;
        __nv_bfloat16* Alo = Ahi + OP_SZ;
        __nv_bfloat16* Bhi = Alo + OP_SZ;
        __nv_bfloat16* Blo = Bhi + OP_SZ;

        #pragma unroll
        for (int j = 0; j < 4; j++) {
            const int row = grow + 32 * j;
            const int idx = row * SSTB + gq * 4;
            float av[4] = {aReg[j].x, aReg[j].y, aReg[j].z, aReg[j].w};
            float bv[4] = {bReg[j].x, bReg[j].y, bReg[j].z, bReg[j].w};
            uint32_t h0, l0, h1, l1;
            split2(av[0], av[1], h0, l0); split2(av[2], av[3], h1, l1);
            *(uint2*)&Ahi[idx] = make_uint2(h0, h1);
            *(uint2*)&Alo[idx] = make_uint2(l0, l1);
            split2(bv[0], bv[1], h0, l0); split2(bv[2], bv[3], h1, l1);
            *(uint2*)&Bhi[idx] = make_uint2(h0, h1);
            *(uint2*)&Blo[idx] = make_uint2(l0, l1);
        }
        __syncthreads();

        if (kt + 1 < NT) {
            const int off = (kt + 1) * BK;
            #pragma unroll
            for (int j = 0; j < 4; j++) {
                aReg[j] = *(const float4*)(Ag + (size_t)(32 * j) * K + off);
                bReg[j] = *(const float4*)(Bg + (size_t)(32 * j) * K + off);
            }
        }

        #pragma unroll
        for (int ks = 0; ks < 2; ks++) {
            const int k0 = ks * 16;
            uint32_t afh[2][4], afl[2][4];
            #pragma unroll
            for (int mt = 0; mt < 2; mt++) {
                const int r0 = (wm + mt * 16 + qr) * SSTB;
                const int r1 = r0 + 8 * SSTB;
                afh[mt][0] = *(const uint32_t*)&Ahi[r0 + k0 + 2 * qk];
                afh[mt][1] = *(const uint32_t*)&Ahi[r1 + k0 + 2 * qk];
                afh[mt][2] = *(const uint32_t*)&Ahi[r0 + k0 + 8 + 2 * qk];
                afh[mt][3] = *(const uint32_t*)&Ahi[r1 + k0 + 8 + 2 * qk];
                afl[mt][0] = *(const uint32_t*)&Alo[r0 + k0 + 2 * qk];
                afl[mt][1] = *(const uint32_t*)&Alo[r1 + k0 + 2 * qk];
                afl[mt][2] = *(const uint32_t*)&Alo[r0 + k0 + 8 + 2 * qk];
                afl[mt][3] = *(const uint32_t*)&Alo[r1 + k0 + 8 + 2 * qk];
            }
            #pragma unroll
            for (int nt = 0; nt < 8; nt++) {
                const int nrow = (wn + nt * 8 + qr) * SSTB;
                uint32_t bfh[2], bfl[2];
                bfh[0] = *(const uint32_t*)&Bhi[nrow + k0 + 2 * qk];
                bfh[1] = *(const uint32_t*)&Bhi[nrow + k0 + 8 + 2 * qk];
                bfl[0] = *(const uint32_t*)&Blo[nrow + k0 + 2 * qk];
                bfl[1] = *(const uint32_t*)&Blo[nrow + k0 + 8 + 2 * qk];
                #pragma unroll
                for (int mt = 0; mt < 2; mt++) {
                    mma_bf16(acc[mt][nt], afh[mt], bfh);
                    mma_bf16(acc[mt][nt], afh[mt], bfl);
                    mma_bf16(acc[mt][nt], afl[mt], bfh);
                }
            }
        }
        __syncthreads();
    }

    #pragma unroll
    for (int mt = 0; mt < 2; mt++) {
        const int r = bm + wm + mt * 16 + qr;
        #pragma unroll
        for (int nt = 0; nt < 8; nt++) {
            const int ncol = bn + wn + nt * 8 + 2 * qk;
            *(float2*)(Cc + (size_t)r * N + ncol) =
                make_float2(acc[mt][nt][0], acc[mt][nt][1]);
            *(float2*)(Cc + (size_t)(r + 8) * N + ncol) =
                make_float2(acc[mt][nt][2], acc[mt][nt][3]);
        }
    }
}

// ---------------------------------------------------------------------------
// Flash attention with split-bf16 mma. CTA = 128 q-rows of one (b,h).
// 8 warps x 16 rows. KV tiles of 64. Q resident in registers (hi/lo).
// ---------------------------------------------------------------------------
#define AST 72   // attention smem row stride (bf16 units)

__global__ __launch_bounds__(256) void attn_mma_kernel(
    const float* __restrict__ qkv, float* __restrict__ outf)
{
    __shared__ __align__(16) __nv_bfloat16 Khi[64 * AST];
    __shared__ __align__(16) __nv_bfloat16 Klo[64 * AST];
    __shared__ __align__(16) __nv_bfloat16 Vthi[64 * AST];
    __shared__ __align__(16) __nv_bfloat16 Vtlo[64 * AST];

    const int tid = threadIdx.x, wid = tid >> 5, lane = tid & 31;
    const int qr = lane >> 2, qk = lane & 3;
    const int qb = blockIdx.x;                 // q block of 128 rows
    const int bh = blockIdx.y;
    const int b = bh >> 4, h = bh & 15;

    const size_t seq0 = (size_t)b * C_SZ;
    const float* kbase = qkv + seq0 * F3 + HD + h * D_SZ;
    const float* vbase = qkv + seq0 * F3 + 2 * HD + h * D_SZ;
    const int wr = qb * 128 + wid * 16;        // warp's first q row in sequence
    const float* qbase = qkv + (seq0 + wr) * F3 + h * D_SZ;

    // Load Q fragments (pre-scaled by 1/sqrt(D)=0.125), split hi/lo
    uint32_t qhi[4][4], qlo[4][4];
    #pragma unroll
    for (int kc = 0; kc < 4; kc++) {
        const int d0 = kc * 16 + 2 * qk;
        float2 v00 = *(const float2*)(qbase + (size_t)qr * F3 + d0);
        float2 v10 = *(const float2*)(qbase + (size_t)(qr + 8) * F3 + d0);
        float2 v01 = *(const float2*)(qbase + (size_t)qr * F3 + d0 + 8);
        float2 v11 = *(const float2*)(qbase + (size_t)(qr + 8) * F3 + d0 + 8);
        split2(v00.x * 0.125f, v00.y * 0.125f, qhi[kc][0], qlo[kc][0]);
        split2(v10.x * 0.125f, v10.y * 0.125f, qhi[kc][1], qlo[kc][1]);
        split2(v01.x * 0.125f, v01.y * 0.125f, qhi[kc][2], qlo[kc][2]);
        split2(v11.x * 0.125f, v11.y * 0.125f, qhi[kc][3], qlo[kc][3]);
    }

    float m0 = -1e30f, m1 = -1e30f, l0 = 0.f, l1 = 0.f;
    float o[8][4];
    #pragma unroll
    for (int nt = 0; nt < 8; nt++)
        #pragma unroll
        for (int v = 0; v < 4; v++) o[nt][v] = 0.f;

    const int nkv = 2 * qb + 2;   // kv tiles of 64 covering causal span

    for (int kb = 0; kb < nkv; kb++) {
        // Stage K (K-major) and V^T (d-major), hi/lo bf16
        #pragma unroll
        for (int j = 0; j < 4; j++) {
            const int idx = tid + 256 * j;
            const int row = idx >> 4;          // kv row 0..63
            const int q4  = idx & 15;          // float4 within row
            const size_t grow = (size_t)(kb * 64 + row) * F3;
            float4 kv4 = *(const float4*)(kbase + grow + q4 * 4);
            float4 vv4 = *(const float4*)(vbase + grow + q4 * 4);
            uint32_t h0, lo0, h1, lo1;
            split2(kv4.x, kv4.y, h0, lo0);
            split2(kv4.z, kv4.w, h1, lo1);
            *(uint2*)&Khi[row * AST + q4 * 4] = make_uint2(h0, h1);
            *(uint2*)&Klo[row * AST + q4 * 4] = make_uint2(lo0, lo1);
            float vv[4] = {vv4.x, vv4.y, vv4.z, vv4.w};
            #pragma unroll
            for (int i = 0; i < 4; i++) {
                __nv_bfloat16 hv = __float2bfloat16(vv[i]);
                __nv_bfloat16 lv = __float2bfloat16(vv[i] - __bfloat162float(hv));
                Vthi[(q4 * 4 + i) * AST + row] = hv;
                Vtlo[(q4 * 4 + i) * AST + row] = lv;
            }
        }
        __syncthreads();

        // S = Q K^T  (16 x 64 per warp)
        float s[8][4];
        #pragma unroll
        for (int nt = 0; nt < 8; nt++)
            #pragma unroll
            for (int v = 0; v < 4; v++) s[nt][v] = 0.f;

        #pragma unroll
        for (int kc = 0; kc < 4; kc++) {
            const int k0 = kc * 16 + 2 * qk;
            #pragma unroll
            for (int nt = 0; nt < 8; nt++) {
                const int nrow = (nt * 8 + qr) * AST;
                uint32_t bfh[2], bfl[2];
                bfh[0] = *(const uint32_t*)&Khi[nrow + k0];
                bfh[1] = *(const uint32_t*)&Khi[nrow + k0 + 8];
                bfl[0] = *(const uint32_t*)&Klo[nrow + k0];
                bfl[1] = *(const uint32_t*)&Klo[nrow + k0 + 8];
                mma_bf16(s[nt], qhi[kc], bfh);
                mma_bf16(s[nt], qhi[kc], bfl);
                mma_bf16(s[nt], qlo[kc], bfh);
            }
        }

        // causal mask (only tiles that straddle the warp's rows)
        if (kb * 64 + 63 > wr) {
            #pragma unroll
            for (int nt = 0; nt < 8; nt++) {
                const int colb = kb * 64 + nt * 8 + 2 * qk;
                const int r0 = wr + qr, r1 = r0 + 8;
                if (colb > r0)     s[nt][0] = -1e30f;
                if (colb + 1 > r0) s[nt][1] = -1e30f;
                if (colb > r1)     s[nt][2] = -1e30f;
                if (colb + 1 > r1) s[nt][3] = -1e30f;
            }
        }

        // online softmax (rows qr -> idx 0,1 ; qr+8 -> idx 2,3)
        {
            float mx0 = -1e30f, mx1 = -1e30f;
            #pragma unroll
            for (int nt = 0; nt < 8; nt++) {
                mx0 = fmaxf(mx0, fmaxf(s[nt][0], s[nt][1]));
                mx1 = fmaxf(mx1, fmaxf(s[nt][2], s[nt][3]));
            }
            mx0 = fmaxf(mx0, __shfl_xor_sync(0xffffffffu, mx0, 1));
            mx0 = fmaxf(mx0, __shfl_xor_sync(0xffffffffu, mx0, 2));
            mx1 = fmaxf(mx1, __shfl_xor_sync(0xffffffffu, mx1, 1));
            mx1 = fmaxf(mx1, __shfl_xor_sync(0xffffffffu, mx1, 2));

            const float mn0 = fmaxf(m0, mx0), mn1 = fmaxf(m1, mx1);
            const float a0 = __expf(m0 - mn0), a1 = __expf(m1 - mn1);
            float s0 = 0.f, s1 = 0.f;
            #pragma unroll
            for (int nt = 0; nt < 8; nt++) {
                s[nt][0] = __expf(s[nt][0] - mn0);
                s[nt][1] = __expf(s[nt][1] - mn0);
                s[nt][2] = __expf(s[nt][2] - mn1);
                s[nt][3] = __expf(s[nt][3] - mn1);
                s0 += s[nt][0] + s[nt][1];
                s1 += s[nt][2] + s[nt][3];
            }
            s0 += __shfl_xor_sync(0xffffffffu, s0, 1);
            s0 += __shfl_xor_sync(0xffffffffu, s0, 2);
            s1 += __shfl_xor_sync(0xffffffffu, s1, 1);
            s1 += __shfl_xor_sync(0xffffffffu, s1, 2);
            l0 = l0 * a0 + s0;  m0 = mn0;
            l1 = l1 * a1 + s1;  m1 = mn1;
            #pragma unroll
            for (int nt = 0; nt < 8; nt++) {
                o[nt][0] *= a0; o[nt][1] *= a0;
                o[nt][2] *= a1; o[nt][3] *= a1;
            }
        }

        // O += P V   (P A-fragments repacked straight from s regs, hi/lo)
        #pragma unroll
        for (int kc = 0; kc < 4; kc++) {
            uint32_t ph[4], pl[4];
            split2(s[2 * kc][0],     s[2 * kc][1],     ph[0], pl[0]);
            split2(s[2 * kc][2],     s[2 * kc][3],     ph[1], pl[1]);
            split2(s[2 * kc + 1][0], s[2 * kc + 1][1], ph[2], pl[2]);
            split2(s[2 * kc + 1][2], s[2 * kc + 1][3], ph[3], pl[3]);
            const int k0 = kc * 16 + 2 * qk;
            #pragma unroll
            for (int nt = 0; nt < 8; nt++) {
                const int nrow = (nt * 8 + qr) * AST;
                uint32_t bfh[2], bfl[2];
                bfh[0] = *(const uint32_t*)&Vthi[nrow + k0];
                bfh[1] = *(const uint32_t*)&Vthi[nrow + k0 + 8];
                bfl[0] = *(const uint32_t*)&Vtlo[nrow + k0];
                bfl[1] = *(const uint32_t*)&Vtlo[nrow + k0 + 8];
                mma_bf16(o[nt], ph, bfh);
                mma_bf16(o[nt], ph, bfl);
                mma_bf16(o[nt], pl, bfh);
            }
        }
        __syncthreads();
    }

    // normalize + store
    const float i0 = 1.f / l0, i1 = 1.f / l1;
    #pragma unroll
    for (int nt = 0; nt < 8; nt++) {
        const int col = h * D_SZ + nt * 8 + 2 * qk;
        const size_t r0 = seq0 + wr + qr, r1 = r0 + 8;
        *(float2*)(outf + r0 * HD + col) = make_float2(o[nt][0] * i0, o[nt][1] * i0);
        *(float2*)(outf + r1 * HD + col) = make_float2(o[nt][2] * i1, o[nt][3] * i1);
    }
}

// ---------------------------------------------------------------------------
extern "C" void kernel_launch(void* const* d_in, const int* in_sizes, int n_in,
                              void* d_out, int out_size)
{
    const float* x     = (const float*)d_in[0];
    const float* w_qkv = (const float*)d_in[1];
    const float* w_out = (const float*)d_in[2];
    float* out = (float*)d_out;

    float *qkv = nullptr, *attn = nullptr;
    cudaGetSymbolAddress((void**)&qkv, g_qkv);
    cudaGetSymbolAddress((void**)&attn, g_attn);

    cudaFuncSetAttribute(gemm_bf16x3_kernel,
                         cudaFuncAttributeMaxDynamicSharedMemorySize, GEMM_SMEM);

    // 1) QKV projection
    {
        dim3 grid(F3 / 128, M_SZ / 128);
        gemm_bf16x3_kernel<<<grid, 256, GEMM_SMEM>>>(x, w_qkv, qkv, M_SZ, F3, E_SZ);
    }

    // 2) causal flash attention (tensor-core)
    {
        dim3 grid(C_SZ / 128, B_SZ * H_SZ);
        attn_mma_kernel<<<grid, 256>>>(qkv, attn);
    }

    // 3) output projection
    {
        dim3 grid(E_SZ / 128, M_SZ / 128);
        gemm_bf16x3_kernel<<<grid, 256, GEMM_SMEM>>>(attn, w_out, out, M_SZ, E_SZ, HD);
    }
}

// round 6
// speedup vs baseline: 2.9101x; 1.1125x over previous
#include <cuda_runtime.h>
#include <cuda_bf16.h>
#include <math.h>
#include <cstdint>

// Problem constants
#define B_SZ 4
#define C_SZ 2048
#define E_SZ 1024
#define H_SZ 16
#define D_SZ 64
#define HD   (H_SZ * D_SZ)     // 1024
#define F3   (3 * HD)          // 3072
#define M_SZ (B_SZ * C_SZ)     // 8192

typedef __nv_bfloat16 bf16;

// Pre-split scratch (bf16 hi/lo pairs)
__device__ bf16 g_xh[(size_t)M_SZ * E_SZ],  g_xl[(size_t)M_SZ * E_SZ];
__device__ bf16 g_wqh[(size_t)F3 * E_SZ],   g_wql[(size_t)F3 * E_SZ];
__device__ bf16 g_woh[(size_t)E_SZ * HD],   g_wol[(size_t)E_SZ * HD];
__device__ bf16 g_qh[(size_t)M_SZ * F3],    g_ql[(size_t)M_SZ * F3];
__device__ bf16 g_ah[(size_t)M_SZ * HD],    g_al[(size_t)M_SZ * HD];

// ---------------------------------------------------------------------------
// Helpers
// ---------------------------------------------------------------------------
__device__ __forceinline__ uint32_t smem_u32(const void* p) {
    uint32_t a;
    asm("{ .reg .u64 t; cvta.to.shared.u64 t, %1; cvt.u32.u64 %0, t; }"
        : "=r"(a) : "l"(p));
    return a;
}
#define CP_ASYNC16(dst, src) \
    asm volatile("cp.async.cg.shared.global [%0], [%1], 16;" \
        :: "r"(dst), "l"(src) : "memory")
#define CP_COMMIT() asm volatile("cp.async.commit_group;" ::: "memory")
#define CP_WAIT(n)  asm volatile("cp.async.wait_group %0;" :: "n"(n) : "memory")

__device__ __forceinline__ void mma_bf16(float* c, const uint32_t* a, const uint32_t* b) {
    asm volatile(
        "mma.sync.aligned.m16n8k16.row.col.f32.bf16.bf16.f32 "
        "{%0,%1,%2,%3}, {%4,%5,%6,%7}, {%8,%9}, {%0,%1,%2,%3};"
        : "+f"(c[0]), "+f"(c[1]), "+f"(c[2]), "+f"(c[3])
        : "r"(a[0]), "r"(a[1]), "r"(a[2]), "r"(a[3]), "r"(b[0]), "r"(b[1]));
}

__device__ __forceinline__ uint32_t pack_bf16(bf16 a, bf16 b) {
    uint16_t lo = __bfloat16_as_ushort(a), hi = __bfloat16_as_ushort(b);
    return ((uint32_t)hi << 16) | lo;
}
__device__ __forceinline__ void split2(float x, float y, uint32_t& hi, uint32_t& lo) {
    bf16 hx = __float2bfloat16(x), hy = __float2bfloat16(y);
    bf16 lx = __float2bfloat16(x - __bfloat162float(hx));
    bf16 ly = __float2bfloat16(y - __bfloat162float(hy));
    hi = pack_bf16(hx, hy);
    lo = pack_bf16(lx, ly);
}

// ---------------------------------------------------------------------------
// Elementwise fp32 -> (hi, lo) bf16 split
// ---------------------------------------------------------------------------
__global__ __launch_bounds__(256) void split_kernel(
    const float* __restrict__ in, bf16* __restrict__ hi, bf16* __restrict__ lo, int n4)
{
    int i = blockIdx.x * 256 + threadIdx.x;
    if (i >= n4) return;
    float4 v = *(const float4*)(in + (size_t)i * 4);
    uint32_t h0, l0, h1, l1;
    split2(v.x, v.y, h0, l0);
    split2(v.z, v.w, h1, l1);
    *(uint2*)(hi + (size_t)i * 4) = make_uint2(h0, h1);
    *(uint2*)(lo + (size_t)i * 4) = make_uint2(l0, l1);
}

// ---------------------------------------------------------------------------
// Pure split-bf16 GEMM: C = A * B^T with A,B given as hi/lo bf16 (K-major).
// BM=BN=128, BK=32, 256 threads, cp.async double-buffered.
// SPLIT_OUT: write hi/lo bf16; else fp32.
// ---------------------------------------------------------------------------
#define SSTB 40
#define OPB (128 * SSTB)            // bf16 units per operand (5120)
#define BUFB (4 * OPB)              // Ahi,Alo,Bhi,Blo per buffer (20480 bf16)
#define GEMM_SMEM (2 * BUFB * 2)    // bytes: 81920

template <bool SPLIT_OUT>
__global__ __launch_bounds__(256, 2) void gemm_bf3_kernel(
    const bf16* __restrict__ Ahi_g, const bf16* __restrict__ Alo_g,
    const bf16* __restrict__ Bhi_g, const bf16* __restrict__ Blo_g,
    float* __restrict__ Cf, bf16* __restrict__ Chi, bf16* __restrict__ Clo,
    int M, int N, int K)
{
    extern __shared__ bf16 sm[];

    const int tid  = threadIdx.x;
    const int wid  = tid >> 5, lane = tid & 31;
    const int bm   = blockIdx.y * 128, bn = blockIdx.x * 128;
    const int wm   = (wid & 3) * 32;
    const int wn   = (wid >> 2) * 64;
    const int qr   = lane >> 2;
    const int qk   = lane & 3;

    // loader mapping: chunk c covers (row=c>>2, q=c&3) of a 128x32 tile; this
    // thread owns chunks tid (rows 0..63) and tid+256 (rows 64..127)
    const int lr0 = tid >> 2;
    const int lq  = tid & 3;

    const bf16* gAh0 = Ahi_g + (size_t)(bm + lr0) * K + lq * 8;
    const bf16* gAl0 = Alo_g + (size_t)(bm + lr0) * K + lq * 8;
    const bf16* gBh0 = Bhi_g + (size_t)(bn + lr0) * K + lq * 8;
    const bf16* gBl0 = Blo_g + (size_t)(bn + lr0) * K + lq * 8;
    const size_t rstep = (size_t)64 * K;

    uint32_t sAh[2], sAl[2], sBh[2], sBl[2];
    #pragma unroll
    for (int b = 0; b < 2; b++) {
        bf16* base = sm + b * BUFB;
        sAh[b] = smem_u32(base + lr0 * SSTB + lq * 8);
        sAl[b] = smem_u32(base + OPB + lr0 * SSTB + lq * 8);
        sBh[b] = smem_u32(base + 2 * OPB + lr0 * SSTB + lq * 8);
        sBl[b] = smem_u32(base + 3 * OPB + lr0 * SSTB + lq * 8);
    }
    const uint32_t sstep = 64 * SSTB * 2;   // byte offset for +64 rows

    float acc[2][8][4];
    #pragma unroll
    for (int mt = 0; mt < 2; mt++)
        #pragma unroll
        for (int nt = 0; nt < 8; nt++)
            #pragma unroll
            for (int v = 0; v < 4; v++) acc[mt][nt][v] = 0.f;

    const int NT = K / 32;

    // prefetch tile 0
    CP_ASYNC16(sAh[0], gAh0);          CP_ASYNC16(sAh[0] + sstep, gAh0 + rstep);
    CP_ASYNC16(sAl[0], gAl0);          CP_ASYNC16(sAl[0] + sstep, gAl0 + rstep);
    CP_ASYNC16(sBh[0], gBh0);          CP_ASYNC16(sBh[0] + sstep, gBh0 + rstep);
    CP_ASYNC16(sBl[0], gBl0);          CP_ASYNC16(sBl[0] + sstep, gBl0 + rstep);
    CP_COMMIT();

    for (int kt = 0; kt < NT; kt++) {
        const int buf = kt & 1;
        if (kt + 1 < NT) {
            const int nb = buf ^ 1;
            const int off = (kt + 1) * 32;
            CP_ASYNC16(sAh[nb], gAh0 + off);  CP_ASYNC16(sAh[nb] + sstep, gAh0 + rstep + off);
            CP_ASYNC16(sAl[nb], gAl0 + off);  CP_ASYNC16(sAl[nb] + sstep, gAl0 + rstep + off);
            CP_ASYNC16(sBh[nb], gBh0 + off);  CP_ASYNC16(sBh[nb] + sstep, gBh0 + rstep + off);
            CP_ASYNC16(sBl[nb], gBl0 + off);  CP_ASYNC16(sBl[nb] + sstep, gBl0 + rstep + off);
            CP_COMMIT();
            CP_WAIT(1);
        } else {
            CP_WAIT(0);
        }
        __syncthreads();

        const bf16* Ahs = sm + buf * BUFB;
        const bf16* Als = Ahs + OPB;
        const bf16* Bhs = Als + OPB;
        const bf16* Bls = Bhs + OPB;

        #pragma unroll
        for (int ks = 0; ks < 2; ks++) {
            const int k0 = ks * 16;
            uint32_t afh[2][4], afl[2][4];
            #pragma unroll
            for (int mt = 0; mt < 2; mt++) {
                const int r0 = (wm + mt * 16 + qr) * SSTB;
                const int r1 = r0 + 8 * SSTB;
                afh[mt][0] = *(const uint32_t*)&Ahs[r0 + k0 + 2 * qk];
                afh[mt][1] = *(const uint32_t*)&Ahs[r1 + k0 + 2 * qk];
                afh[mt][2] = *(const uint32_t*)&Ahs[r0 + k0 + 8 + 2 * qk];
                afh[mt][3] = *(const uint32_t*)&Ahs[r1 + k0 + 8 + 2 * qk];
                afl[mt][0] = *(const uint32_t*)&Als[r0 + k0 + 2 * qk];
                afl[mt][1] = *(const uint32_t*)&Als[r1 + k0 + 2 * qk];
                afl[mt][2] = *(const uint32_t*)&Als[r0 + k0 + 8 + 2 * qk];
                afl[mt][3] = *(const uint32_t*)&Als[r1 + k0 + 8 + 2 * qk];
            }
            #pragma unroll
            for (int nt = 0; nt < 8; nt++) {
                const int nrow = (wn + nt * 8 + qr) * SSTB;
                uint32_t bfh[2], bfl[2];
                bfh[0] = *(const uint32_t*)&Bhs[nrow + k0 + 2 * qk];
                bfh[1] = *(const uint32_t*)&Bhs[nrow + k0 + 8 + 2 * qk];
                bfl[0] = *(const uint32_t*)&Bls[nrow + k0 + 2 * qk];
                bfl[1] = *(const uint32_t*)&Bls[nrow + k0 + 8 + 2 * qk];
                #pragma unroll
                for (int mt = 0; mt < 2; mt++) {
                    mma_bf16(acc[mt][nt], afh[mt], bfh);
                    mma_bf16(acc[mt][nt], afh[mt], bfl);
                    mma_bf16(acc[mt][nt], afl[mt], bfh);
                }
            }
        }
        __syncthreads();
    }

    // epilogue
    #pragma unroll
    for (int mt = 0; mt < 2; mt++) {
        const int r = bm + wm + mt * 16 + qr;
        #pragma unroll
        for (int nt = 0; nt < 8; nt++) {
            const int ncol = bn + wn + nt * 8 + 2 * qk;
            if (SPLIT_OUT) {
                uint32_t h, l;
                split2(acc[mt][nt][0], acc[mt][nt][1], h, l);
                *(uint32_t*)(Chi + (size_t)r * N + ncol) = h;
                *(uint32_t*)(Clo + (size_t)r * N + ncol) = l;
                split2(acc[mt][nt][2], acc[mt][nt][3], h, l);
                *(uint32_t*)(Chi + (size_t)(r + 8) * N + ncol) = h;
                *(uint32_t*)(Clo + (size_t)(r + 8) * N + ncol) = l;
            } else {
                *(float2*)(Cf + (size_t)r * N + ncol) =
                    make_float2(acc[mt][nt][0], acc[mt][nt][1]);
                *(float2*)(Cf + (size_t)(r + 8) * N + ncol) =
                    make_float2(acc[mt][nt][2], acc[mt][nt][3]);
            }
        }
    }
}

// ---------------------------------------------------------------------------
// Flash attention, all-bf16 inputs (pre-split qkv). CTA = 128 q-rows.
// ---------------------------------------------------------------------------
#define AST 72

__global__ __launch_bounds__(256) void attn_mma_kernel(
    const bf16* __restrict__ qh, const bf16* __restrict__ ql,
    bf16* __restrict__ ah, bf16* __restrict__ al)
{
    __shared__ __align__(16) bf16 Khi[64 * AST];
    __shared__ __align__(16) bf16 Klo[64 * AST];
    __shared__ __align__(16) bf16 Vthi[64 * AST];
    __shared__ __align__(16) bf16 Vtlo[64 * AST];

    const int tid = threadIdx.x, wid = tid >> 5, lane = tid & 31;
    const int qr = lane >> 2, qk = lane & 3;
    const int qb = blockIdx.x;
    const int bh = blockIdx.y;
    const int b = bh >> 4, h = bh & 15;

    const size_t seq0 = (size_t)b * C_SZ;
    const int wr = qb * 128 + wid * 16;

    // K/V loader mapping: chunk c = (row=c>>3, q=c&7); thread owns c=tid (rows
    // 0..31) and c=tid+256 (rows 32..63)
    const int kr0 = tid >> 3;
    const int kq  = tid & 7;
    const uint32_t sKh0 = smem_u32(Khi + kr0 * AST + kq * 8);
    const uint32_t sKl0 = smem_u32(Klo + kr0 * AST + kq * 8);
    const uint32_t kstep = 32 * AST * 2;   // +32 rows in bytes

    // Q fragments from pre-split qkv (scale applied post-mma)
    uint32_t qhi[4][4], qlo[4][4];
    {
        const bf16* qb0 = qh + (seq0 + wr) * F3 + h * D_SZ;
        const bf16* qb1 = ql + (seq0 + wr) * F3 + h * D_SZ;
        #pragma unroll
        for (int kc = 0; kc < 4; kc++) {
            const int d0 = kc * 16 + 2 * qk;
            qhi[kc][0] = *(const uint32_t*)(qb0 + (size_t)qr * F3 + d0);
            qhi[kc][1] = *(const uint32_t*)(qb0 + (size_t)(qr + 8) * F3 + d0);
            qhi[kc][2] = *(const uint32_t*)(qb0 + (size_t)qr * F3 + d0 + 8);
            qhi[kc][3] = *(const uint32_t*)(qb0 + (size_t)(qr + 8) * F3 + d0 + 8);
            qlo[kc][0] = *(const uint32_t*)(qb1 + (size_t)qr * F3 + d0);
            qlo[kc][1] = *(const uint32_t*)(qb1 + (size_t)(qr + 8) * F3 + d0);
            qlo[kc][2] = *(const uint32_t*)(qb1 + (size_t)qr * F3 + d0 + 8);
            qlo[kc][3] = *(const uint32_t*)(qb1 + (size_t)(qr + 8) * F3 + d0 + 8);
        }
    }

    float m0 = -1e30f, m1 = -1e30f, l0 = 0.f, l1 = 0.f;
    float o[8][4];
    #pragma unroll
    for (int nt = 0; nt < 8; nt++)
        #pragma unroll
        for (int v = 0; v < 4; v++) o[nt][v] = 0.f;

    const int nkv = 2 * qb + 2;

    for (int kb = 0; kb < nkv; kb++) {
        const size_t krow0 = (seq0 + kb * 64 + kr0) * F3;
        const bf16* gKh = qh + krow0 + HD + h * D_SZ + kq * 8;
        const bf16* gKl = ql + krow0 + HD + h * D_SZ + kq * 8;
        const size_t kr32 = (size_t)32 * F3;

        CP_ASYNC16(sKh0, gKh);          CP_ASYNC16(sKh0 + kstep, gKh + kr32);
        CP_ASYNC16(sKl0, gKl);          CP_ASYNC16(sKl0 + kstep, gKl + kr32);
        CP_COMMIT();

        // V^T staging (raw ushort scatter, no conversion)
        {
            const bf16* gVh = qh + krow0 + 2 * HD + h * D_SZ + kq * 8;
            const bf16* gVl = ql + krow0 + 2 * HD + h * D_SZ + kq * 8;
            #pragma unroll
            for (int half = 0; half < 2; half++) {
                const int row = kr0 + 32 * half;
                uint4 vh = *(const uint4*)(gVh + half * kr32);
                uint4 vl = *(const uint4*)(gVl + half * kr32);
                const uint16_t* ph = (const uint16_t*)&vh;
                const uint16_t* pl = (const uint16_t*)&vl;
                #pragma unroll
                for (int i = 0; i < 8; i++) {
                    ((uint16_t*)Vthi)[(kq * 8 + i) * AST + row] = ph[i];
                    ((uint16_t*)Vtlo)[(kq * 8 + i) * AST + row] = pl[i];
                }
            }
        }
        CP_WAIT(0);
        __syncthreads();

        // S = Q K^T
        float s[8][4];
        #pragma unroll
        for (int nt = 0; nt < 8; nt++)
            #pragma unroll
            for (int v = 0; v < 4; v++) s[nt][v] = 0.f;

        #pragma unroll
        for (int kc = 0; kc < 4; kc++) {
            const int k0 = kc * 16 + 2 * qk;
            #pragma unroll
            for (int nt = 0; nt < 8; nt++) {
                const int nrow = (nt * 8 + qr) * AST;
                uint32_t bfh[2], bfl[2];
                bfh[0] = *(const uint32_t*)&Khi[nrow + k0];
                bfh[1] = *(const uint32_t*)&Khi[nrow + k0 + 8];
                bfl[0] = *(const uint32_t*)&Klo[nrow + k0];
                bfl[1] = *(const uint32_t*)&Klo[nrow + k0 + 8];
                mma_bf16(s[nt], qhi[kc], bfh);
                mma_bf16(s[nt], qhi[kc], bfl);
                mma_bf16(s[nt], qlo[kc], bfh);
            }
        }

        // scale + causal mask
        const bool edge = (kb * 64 + 63 > wr);
        #pragma unroll
        for (int nt = 0; nt < 8; nt++) {
            #pragma unroll
            for (int v = 0; v < 4; v++) s[nt][v] *= 0.125f;
            if (edge) {
                const int colb = kb * 64 + nt * 8 + 2 * qk;
                const int r0 = wr + qr, r1 = r0 + 8;
                if (colb > r0)     s[nt][0] = -1e30f;
                if (colb + 1 > r0) s[nt][1] = -1e30f;
                if (colb > r1)     s[nt][2] = -1e30f;
                if (colb + 1 > r1) s[nt][3] = -1e30f;
            }
        }

        // online softmax
        {
            float mx0 = -1e30f, mx1 = -1e30f;
            #pragma unroll
            for (int nt = 0; nt < 8; nt++) {
                mx0 = fmaxf(mx0, fmaxf(s[nt][0], s[nt][1]));
                mx1 = fmaxf(mx1, fmaxf(s[nt][2], s[nt][3]));
            }
            mx0 = fmaxf(mx0, __shfl_xor_sync(0xffffffffu, mx0, 1));
            mx0 = fmaxf(mx0, __shfl_xor_sync(0xffffffffu, mx0, 2));
            mx1 = fmaxf(mx1, __shfl_xor_sync(0xffffffffu, mx1, 1));
            mx1 = fmaxf(mx1, __shfl_xor_sync(0xffffffffu, mx1, 2));

            const float mn0 = fmaxf(m0, mx0), mn1 = fmaxf(m1, mx1);
            const float a0 = __expf(m0 - mn0), a1 = __expf(m1 - mn1);
            float s0 = 0.f, s1 = 0.f;
            #pragma unroll
            for (int nt = 0; nt < 8; nt++) {
                s[nt][0] = __expf(s[nt][0] - mn0);
                s[nt][1] = __expf(s[nt][1] - mn0);
                s[nt][2] = __expf(s[nt][2] - mn1);
                s[nt][3] = __expf(s[nt][3] - mn1);
                s0 += s[nt][0] + s[nt][1];
                s1 += s[nt][2] + s[nt][3];
            }
            s0 += __shfl_xor_sync(0xffffffffu, s0, 1);
            s0 += __shfl_xor_sync(0xffffffffu, s0, 2);
            s1 += __shfl_xor_sync(0xffffffffu, s1, 1);
            s1 += __shfl_xor_sync(0xffffffffu, s1, 2);
            l0 = l0 * a0 + s0;  m0 = mn0;
            l1 = l1 * a1 + s1;  m1 = mn1;
            #pragma unroll
            for (int nt = 0; nt < 8; nt++) {
                o[nt][0] *= a0; o[nt][1] *= a0;
                o[nt][2] *= a1; o[nt][3] *= a1;
            }
        }

        // O += P V
        #pragma unroll
        for (int kc = 0; kc < 4; kc++) {
            uint32_t ph[4], pl[4];
            split2(s[2 * kc][0],     s[2 * kc][1],     ph[0], pl[0]);
            split2(s[2 * kc][2],     s[2 * kc][3],     ph[1], pl[1]);
            split2(s[2 * kc + 1][0], s[2 * kc + 1][1], ph[2], pl[2]);
            split2(s[2 * kc + 1][2], s[2 * kc + 1][3], ph[3], pl[3]);
            const int k0 = kc * 16 + 2 * qk;
            #pragma unroll
            for (int nt = 0; nt < 8; nt++) {
                const int nrow = (nt * 8 + qr) * AST;
                uint32_t bfh[2], bfl[2];
                bfh[0] = *(const uint32_t*)&Vthi[nrow + k0];
                bfh[1] = *(const uint32_t*)&Vthi[nrow + k0 + 8];
                bfl[0] = *(const uint32_t*)&Vtlo[nrow + k0];
                bfl[1] = *(const uint32_t*)&Vtlo[nrow + k0 + 8];
                mma_bf16(o[nt], ph, bfh);
                mma_bf16(o[nt], ph, bfl);
                mma_bf16(o[nt], pl, bfh);
            }
        }
        __syncthreads();
    }

    // normalize + split-store
    const float i0 = 1.f / l0, i1 = 1.f / l1;
    #pragma unroll
    for (int nt = 0; nt < 8; nt++) {
        const int col = h * D_SZ + nt * 8 + 2 * qk;
        const size_t r0 = seq0 + wr + qr, r1 = r0 + 8;
        uint32_t hh, ll;
        split2(o[nt][0] * i0, o[nt][1] * i0, hh, ll);
        *(uint32_t*)(ah + r0 * HD + col) = hh;
        *(uint32_t*)(al + r0 * HD + col) = ll;
        split2(o[nt][2] * i1, o[nt][3] * i1, hh, ll);
        *(uint32_t*)(ah + r1 * HD + col) = hh;
        *(uint32_t*)(al + r1 * HD + col) = ll;
    }
}

// ---------------------------------------------------------------------------
extern "C" void kernel_launch(void* const* d_in, const int* in_sizes, int n_in,
                              void* d_out, int out_size)
{
    const float* x     = (const float*)d_in[0];
    const float* w_qkv = (const float*)d_in[1];
    const float* w_out = (const float*)d_in[2];
    float* out = (float*)d_out;

    bf16 *xh, *xl, *wqh, *wql, *woh, *wol, *qh, *ql, *ahp, *alp;
    cudaGetSymbolAddress((void**)&xh,  g_xh);  cudaGetSymbolAddress((void**)&xl,  g_xl);
    cudaGetSymbolAddress((void**)&wqh, g_wqh); cudaGetSymbolAddress((void**)&wql, g_wql);
    cudaGetSymbolAddress((void**)&woh, g_woh); cudaGetSymbolAddress((void**)&wol, g_wol);
    cudaGetSymbolAddress((void**)&qh,  g_qh);  cudaGetSymbolAddress((void**)&ql,  g_ql);
    cudaGetSymbolAddress((void**)&ahp, g_ah);  cudaGetSymbolAddress((void**)&alp, g_al);

    cudaFuncSetAttribute(gemm_bf3_kernel<true>,
                         cudaFuncAttributeMaxDynamicSharedMemorySize, GEMM_SMEM);
    cudaFuncSetAttribute(gemm_bf3_kernel<false>,
                         cudaFuncAttributeMaxDynamicSharedMemorySize, GEMM_SMEM);

    // 0) split inputs once
    {
        int n4 = (M_SZ * E_SZ) / 4;
        split_kernel<<<(n4 + 255) / 256, 256>>>(x, xh, xl, n4);
        n4 = (F3 * E_SZ) / 4;
        split_kernel<<<(n4 + 255) / 256, 256>>>(w_qkv, wqh, wql, n4);
        n4 = (E_SZ * HD) / 4;
        split_kernel<<<(n4 + 255) / 256, 256>>>(w_out, woh, wol, n4);
    }

    // 1) QKV projection -> split bf16 qkv
    {
        dim3 grid(F3 / 128, M_SZ / 128);
        gemm_bf3_kernel<true><<<grid, 256, GEMM_SMEM>>>(
            xh, xl, wqh, wql, nullptr, qh, ql, M_SZ, F3, E_SZ);
    }

    // 2) causal flash attention -> split bf16 attn
    {
        dim3 grid(C_SZ / 128, B_SZ * H_SZ);
        attn_mma_kernel<<<grid, 256>>>(qh, ql, ahp, alp);
    }

    // 3) output projection -> fp32 out
    {
        dim3 grid(E_SZ / 128, M_SZ / 128);
        gemm_bf3_kernel<false><<<grid, 256, GEMM_SMEM>>>(
            ahp, alp, woh, wol, out, nullptr, nullptr, M_SZ, E_SZ, HD);
    }
}

// round 7
// speedup vs baseline: 3.3128x; 1.1384x over previous
#include <cuda_runtime.h>
#include <cuda_bf16.h>
#include <math.h>
#include <cstdint>

// Problem constants
#define B_SZ 4
#define C_SZ 2048
#define E_SZ 1024
#define H_SZ 16
#define D_SZ 64
#define HD   (H_SZ * D_SZ)     // 1024
#define F3   (3 * HD)          // 3072
#define M_SZ (B_SZ * C_SZ)     // 8192

typedef __nv_bfloat16 bf16;

// Pre-split scratch (bf16 hi/lo pairs)
__device__ bf16 g_xh[(size_t)M_SZ * E_SZ],  g_xl[(size_t)M_SZ * E_SZ];
__device__ bf16 g_wqh[(size_t)F3 * E_SZ],   g_wql[(size_t)F3 * E_SZ];
__device__ bf16 g_woh[(size_t)E_SZ * HD],   g_wol[(size_t)E_SZ * HD];
__device__ bf16 g_qh[(size_t)M_SZ * F3],    g_ql[(size_t)M_SZ * F3];
__device__ bf16 g_ah[(size_t)M_SZ * HD],    g_al[(size_t)M_SZ * HD];

// ---------------------------------------------------------------------------
// Helpers
// ---------------------------------------------------------------------------
__device__ __forceinline__ uint32_t smem_u32(const void* p) {
    uint32_t a;
    asm("{ .reg .u64 t; cvta.to.shared.u64 t, %1; cvt.u32.u64 %0, t; }"
        : "=r"(a) : "l"(p));
    return a;
}
#define CP_ASYNC16(dst, src) \
    asm volatile("cp.async.cg.shared.global [%0], [%1], 16;" \
        :: "r"(dst), "l"(src) : "memory")
#define CP_COMMIT() asm volatile("cp.async.commit_group;" ::: "memory")
#define CP_WAIT(n)  asm volatile("cp.async.wait_group %0;" :: "n"(n) : "memory")

__device__ __forceinline__ void mma_bf16(float* c, const uint32_t* a, const uint32_t* b) {
    asm volatile(
        "mma.sync.aligned.m16n8k16.row.col.f32.bf16.bf16.f32 "
        "{%0,%1,%2,%3}, {%4,%5,%6,%7}, {%8,%9}, {%0,%1,%2,%3};"
        : "+f"(c[0]), "+f"(c[1]), "+f"(c[2]), "+f"(c[3])
        : "r"(a[0]), "r"(a[1]), "r"(a[2]), "r"(a[3]), "r"(b[0]), "r"(b[1]));
}

__device__ __forceinline__ void ldsm4(uint32_t* r, uint32_t addr) {
    asm volatile("ldmatrix.sync.aligned.m8n8.x4.shared.b16 {%0,%1,%2,%3}, [%4];"
        : "=r"(r[0]), "=r"(r[1]), "=r"(r[2]), "=r"(r[3]) : "r"(addr));
}
__device__ __forceinline__ void ldsm4t(uint32_t* r, uint32_t addr) {
    asm volatile("ldmatrix.sync.aligned.m8n8.x4.trans.shared.b16 {%0,%1,%2,%3}, [%4];"
        : "=r"(r[0]), "=r"(r[1]), "=r"(r[2]), "=r"(r[3]) : "r"(addr));
}

__device__ __forceinline__ uint32_t pack_bf16(bf16 a, bf16 b) {
    uint16_t lo = __bfloat16_as_ushort(a), hi = __bfloat16_as_ushort(b);
    return ((uint32_t)hi << 16) | lo;
}
__device__ __forceinline__ void split2(float x, float y, uint32_t& hi, uint32_t& lo) {
    bf16 hx = __float2bfloat16(x), hy = __float2bfloat16(y);
    bf16 lx = __float2bfloat16(x - __bfloat162float(hx));
    bf16 ly = __float2bfloat16(y - __bfloat162float(hy));
    hi = pack_bf16(hx, hy);
    lo = pack_bf16(lx, ly);
}

// ---------------------------------------------------------------------------
// Elementwise fp32 -> (hi, lo) bf16 split
// ---------------------------------------------------------------------------
__global__ __launch_bounds__(256) void split_kernel(
    const float* __restrict__ in, bf16* __restrict__ hi, bf16* __restrict__ lo, int n4)
{
    int i = blockIdx.x * 256 + threadIdx.x;
    if (i >= n4) return;
    float4 v = *(const float4*)(in + (size_t)i * 4);
    uint32_t h0, l0, h1, l1;
    split2(v.x, v.y, h0, l0);
    split2(v.z, v.w, h1, l1);
    *(uint2*)(hi + (size_t)i * 4) = make_uint2(h0, h1);
    *(uint2*)(lo + (size_t)i * 4) = make_uint2(l0, l1);
}

// ---------------------------------------------------------------------------
// Pure split-bf16 GEMM with ldmatrix: C = A * B^T (A,B pre-split hi/lo K-major)
// BM=BN=128, BK=32, 256 threads, cp.async double-buffered.
// ---------------------------------------------------------------------------
#define SSTB 40
#define OPB (128 * SSTB)            // bf16 units per operand (5120)
#define BUFB (4 * OPB)              // Ahi,Alo,Bhi,Blo per buffer
#define GEMM_SMEM (2 * BUFB * 2)    // bytes: 81920

template <bool SPLIT_OUT>
__global__ __launch_bounds__(256, 2) void gemm_bf3_kernel(
    const bf16* __restrict__ Ahi_g, const bf16* __restrict__ Alo_g,
    const bf16* __restrict__ Bhi_g, const bf16* __restrict__ Blo_g,
    float* __restrict__ Cf, bf16* __restrict__ Chi, bf16* __restrict__ Clo,
    int M, int N, int K)
{
    extern __shared__ bf16 sm[];
    const uint32_t smb = smem_u32(sm);

    const int tid  = threadIdx.x;
    const int wid  = tid >> 5, lane = tid & 31;
    const int bm   = blockIdx.y * 128, bn = blockIdx.x * 128;
    const int wm   = (wid & 3) * 32;
    const int wn   = (wid >> 2) * 64;
    const int qr   = lane >> 2;
    const int qk   = lane & 3;

    // ldmatrix lane geometry
    const int t8 = lane >> 3, r8 = lane & 7;
    const int a_r = ((t8 & 1) << 3) + r8;     // A: t1,t3 -> +8 rows
    const int a_c = (t8 >> 1) << 3;           // A: t2,t3 -> +8 cols
    const int b_r = ((t8 >> 1) << 3) + r8;    // B: t2,t3 -> +8 rows (n)
    const int b_c = (t8 & 1) << 3;            // B: t1,t3 -> +8 cols (k)

    // loader mapping: row = tid>>2 (0..63, +64), 16B chunk = tid&3
    const int lr0 = tid >> 2;
    const int lq  = tid & 3;

    const bf16* gAh0 = Ahi_g + (size_t)(bm + lr0) * K + lq * 8;
    const bf16* gAl0 = Alo_g + (size_t)(bm + lr0) * K + lq * 8;
    const bf16* gBh0 = Bhi_g + (size_t)(bn + lr0) * K + lq * 8;
    const bf16* gBl0 = Blo_g + (size_t)(bn + lr0) * K + lq * 8;
    const size_t rstep = (size_t)64 * K;

    uint32_t sAh[2], sAl[2], sBh[2], sBl[2];
    #pragma unroll
    for (int b = 0; b < 2; b++) {
        const uint32_t base = smb + b * BUFB * 2;
        sAh[b] = base + (lr0 * SSTB + lq * 8) * 2;
        sAl[b] = sAh[b] + OPB * 2;
        sBh[b] = sAl[b] + OPB * 2;
        sBl[b] = sBh[b] + OPB * 2;
    }
    const uint32_t sstep = 64 * SSTB * 2;

    float acc[2][8][4];
    #pragma unroll
    for (int mt = 0; mt < 2; mt++)
        #pragma unroll
        for (int nt = 0; nt < 8; nt++)
            #pragma unroll
            for (int v = 0; v < 4; v++) acc[mt][nt][v] = 0.f;

    const int NT = K / 32;

    CP_ASYNC16(sAh[0], gAh0);  CP_ASYNC16(sAh[0] + sstep, gAh0 + rstep);
    CP_ASYNC16(sAl[0], gAl0);  CP_ASYNC16(sAl[0] + sstep, gAl0 + rstep);
    CP_ASYNC16(sBh[0], gBh0);  CP_ASYNC16(sBh[0] + sstep, gBh0 + rstep);
    CP_ASYNC16(sBl[0], gBl0);  CP_ASYNC16(sBl[0] + sstep, gBl0 + rstep);
    CP_COMMIT();

    for (int kt = 0; kt < NT; kt++) {
        const int buf = kt & 1;
        if (kt + 1 < NT) {
            const int nb = buf ^ 1;
            const int off = (kt + 1) * 32;
            CP_ASYNC16(sAh[nb], gAh0 + off);  CP_ASYNC16(sAh[nb] + sstep, gAh0 + rstep + off);
            CP_ASYNC16(sAl[nb], gAl0 + off);  CP_ASYNC16(sAl[nb] + sstep, gAl0 + rstep + off);
            CP_ASYNC16(sBh[nb], gBh0 + off);  CP_ASYNC16(sBh[nb] + sstep, gBh0 + rstep + off);
            CP_ASYNC16(sBl[nb], gBl0 + off);  CP_ASYNC16(sBl[nb] + sstep, gBl0 + rstep + off);
            CP_COMMIT();
            CP_WAIT(1);
        } else {
            CP_WAIT(0);
        }
        __syncthreads();

        // smem base (bytes) of each operand in this buffer
        const uint32_t bAh = smb + buf * BUFB * 2;
        const uint32_t bAl = bAh + OPB * 2;
        const uint32_t bBh = bAl + OPB * 2;
        const uint32_t bBl = bBh + OPB * 2;

        #pragma unroll
        for (int ks = 0; ks < 2; ks++) {
            const int k0 = ks * 16;
            uint32_t afh[2][4], afl[2][4];
            #pragma unroll
            for (int mt = 0; mt < 2; mt++) {
                const uint32_t aoff = ((wm + mt * 16 + a_r) * SSTB + k0 + a_c) * 2;
                ldsm4(afh[mt], bAh + aoff);
                ldsm4(afl[mt], bAl + aoff);
            }
            #pragma unroll
            for (int p = 0; p < 4; p++) {
                const uint32_t boff = ((wn + p * 16 + b_r) * SSTB + k0 + b_c) * 2;
                uint32_t bh4[4], bl4[4];
                ldsm4(bh4, bBh + boff);
                ldsm4(bl4, bBl + boff);
                // term-major: same-acc reuse distance = 4
                #pragma unroll
                for (int mt = 0; mt < 2; mt++) {
                    mma_bf16(acc[mt][2 * p],     afh[mt], bh4);
                    mma_bf16(acc[mt][2 * p + 1], afh[mt], bh4 + 2);
                }
                #pragma unroll
                for (int mt = 0; mt < 2; mt++) {
                    mma_bf16(acc[mt][2 * p],     afh[mt], bl4);
                    mma_bf16(acc[mt][2 * p + 1], afh[mt], bl4 + 2);
                }
                #pragma unroll
                for (int mt = 0; mt < 2; mt++) {
                    mma_bf16(acc[mt][2 * p],     afl[mt], bh4);
                    mma_bf16(acc[mt][2 * p + 1], afl[mt], bh4 + 2);
                }
            }
        }
        __syncthreads();
    }

    // epilogue
    #pragma unroll
    for (int mt = 0; mt < 2; mt++) {
        const int r = bm + wm + mt * 16 + qr;
        #pragma unroll
        for (int nt = 0; nt < 8; nt++) {
            const int ncol = bn + wn + nt * 8 + 2 * qk;
            if (SPLIT_OUT) {
                uint32_t h, l;
                split2(acc[mt][nt][0], acc[mt][nt][1], h, l);
                *(uint32_t*)(Chi + (size_t)r * N + ncol) = h;
                *(uint32_t*)(Clo + (size_t)r * N + ncol) = l;
                split2(acc[mt][nt][2], acc[mt][nt][3], h, l);
                *(uint32_t*)(Chi + (size_t)(r + 8) * N + ncol) = h;
                *(uint32_t*)(Clo + (size_t)(r + 8) * N + ncol) = l;
            } else {
                *(float2*)(Cf + (size_t)r * N + ncol) =
                    make_float2(acc[mt][nt][0], acc[mt][nt][1]);
                *(float2*)(Cf + (size_t)(r + 8) * N + ncol) =
                    make_float2(acc[mt][nt][2], acc[mt][nt][3]);
            }
        }
    }
}

// ---------------------------------------------------------------------------
// Flash attention, all-bf16 (pre-split qkv), ldmatrix fragments.
// CTA = 128 q-rows of one (b,h); V staged row-major, read via ldmatrix.trans.
// ---------------------------------------------------------------------------
#define AST 72

__global__ __launch_bounds__(256) void attn_mma_kernel(
    const bf16* __restrict__ qh, const bf16* __restrict__ ql,
    bf16* __restrict__ ah, bf16* __restrict__ al)
{
    __shared__ __align__(16) bf16 Khi[64 * AST];
    __shared__ __align__(16) bf16 Klo[64 * AST];
    __shared__ __align__(16) bf16 Vhi[64 * AST];
    __shared__ __align__(16) bf16 Vlo[64 * AST];

    const int tid = threadIdx.x, wid = tid >> 5, lane = tid & 31;
    const int qr = lane >> 2, qk = lane & 3;
    const int qb = blockIdx.x;
    const int bh = blockIdx.y;
    const int b = bh >> 4, h = bh & 15;

    const size_t seq0 = (size_t)b * C_SZ;
    const int wr = qb * 128 + wid * 16;

    // ldmatrix lane geometry
    const int t8 = lane >> 3, r8 = lane & 7;
    const int kb_r = ((t8 >> 1) << 3) + r8;   // K (B-op): n rows
    const int kb_c = (t8 & 1) << 3;           // K: k cols
    const int vb_r = ((t8 & 1) << 3) + r8;    // V (trans): kv rows
    const int vb_c = (t8 >> 1) << 3;          // V: d cols

    const uint32_t uKhi = smem_u32(Khi), uKlo = smem_u32(Klo);
    const uint32_t uVhi = smem_u32(Vhi), uVlo = smem_u32(Vlo);

    // loader mapping: row = tid>>3 (0..31, +32), 16B chunk = tid&7
    const int kr0 = tid >> 3;
    const int kq  = tid & 7;
    const uint32_t soff = (kr0 * AST + kq * 8) * 2;
    const uint32_t kstep = 32 * AST * 2;

    // Q fragments (pre-split; scale applied post-mma)
    uint32_t qhi[4][4], qlo[4][4];
    {
        const bf16* qb0 = qh + (seq0 + wr) * F3 + h * D_SZ;
        const bf16* qb1 = ql + (seq0 + wr) * F3 + h * D_SZ;
        #pragma unroll
        for (int kc = 0; kc < 4; kc++) {
            const int d0 = kc * 16 + 2 * qk;
            qhi[kc][0] = *(const uint32_t*)(qb0 + (size_t)qr * F3 + d0);
            qhi[kc][1] = *(const uint32_t*)(qb0 + (size_t)(qr + 8) * F3 + d0);
            qhi[kc][2] = *(const uint32_t*)(qb0 + (size_t)qr * F3 + d0 + 8);
            qhi[kc][3] = *(const uint32_t*)(qb0 + (size_t)(qr + 8) * F3 + d0 + 8);
            qlo[kc][0] = *(const uint32_t*)(qb1 + (size_t)qr * F3 + d0);
            qlo[kc][1] = *(const uint32_t*)(qb1 + (size_t)(qr + 8) * F3 + d0);
            qlo[kc][2] = *(const uint32_t*)(qb1 + (size_t)qr * F3 + d0 + 8);
            qlo[kc][3] = *(const uint32_t*)(qb1 + (size_t)(qr + 8) * F3 + d0 + 8);
        }
    }

    float m0 = -1e30f, m1 = -1e30f, l0 = 0.f, l1 = 0.f;
    float o[8][4];
    #pragma unroll
    for (int nt = 0; nt < 8; nt++)
        #pragma unroll
        for (int v = 0; v < 4; v++) o[nt][v] = 0.f;

    const int nkv = 2 * qb + 2;

    for (int kb = 0; kb < nkv; kb++) {
        // stage K and V (both row-major kv x d), hi/lo, via cp.async
        {
            const size_t krow0 = (seq0 + kb * 64 + kr0) * F3;
            const size_t kr32 = (size_t)32 * F3;
            const bf16* gKh = qh + krow0 + HD + h * D_SZ + kq * 8;
            const bf16* gKl = ql + krow0 + HD + h * D_SZ + kq * 8;
            const bf16* gVh = qh + krow0 + 2 * HD + h * D_SZ + kq * 8;
            const bf16* gVl = ql + krow0 + 2 * HD + h * D_SZ + kq * 8;
            CP_ASYNC16(uKhi + soff, gKh);          CP_ASYNC16(uKhi + soff + kstep, gKh + kr32);
            CP_ASYNC16(uKlo + soff, gKl);          CP_ASYNC16(uKlo + soff + kstep, gKl + kr32);
            CP_ASYNC16(uVhi + soff, gVh);          CP_ASYNC16(uVhi + soff + kstep, gVh + kr32);
            CP_ASYNC16(uVlo + soff, gVl);          CP_ASYNC16(uVlo + soff + kstep, gVl + kr32);
            CP_COMMIT();
        }
        CP_WAIT(0);
        __syncthreads();

        // per-warp skip of fully-masked tiles
        if (kb * 64 <= wr + 15) {
            // S = Q K^T
            float s[8][4];
            #pragma unroll
            for (int nt = 0; nt < 8; nt++)
                #pragma unroll
                for (int v = 0; v < 4; v++) s[nt][v] = 0.f;

            #pragma unroll
            for (int kc = 0; kc < 4; kc++) {
                const int k0 = kc * 16;
                #pragma unroll
                for (int p = 0; p < 4; p++) {
                    const uint32_t boff = ((p * 16 + kb_r) * AST + k0 + kb_c) * 2;
                    uint32_t bh4[4], bl4[4];
                    ldsm4(bh4, uKhi + boff);
                    ldsm4(bl4, uKlo + boff);
                    mma_bf16(s[2 * p],     qhi[kc], bh4);
                    mma_bf16(s[2 * p + 1], qhi[kc], bh4 + 2);
                    mma_bf16(s[2 * p],     qhi[kc], bl4);
                    mma_bf16(s[2 * p + 1], qhi[kc], bl4 + 2);
                    mma_bf16(s[2 * p],     qlo[kc], bh4);
                    mma_bf16(s[2 * p + 1], qlo[kc], bh4 + 2);
                }
            }

            // scale + causal mask
            const bool edge = (kb * 64 + 63 > wr);
            #pragma unroll
            for (int nt = 0; nt < 8; nt++) {
                #pragma unroll
                for (int v = 0; v < 4; v++) s[nt][v] *= 0.125f;
                if (edge) {
                    const int colb = kb * 64 + nt * 8 + 2 * qk;
                    const int r0 = wr + qr, r1 = r0 + 8;
                    if (colb > r0)     s[nt][0] = -1e30f;
                    if (colb + 1 > r0) s[nt][1] = -1e30f;
                    if (colb > r1)     s[nt][2] = -1e30f;
                    if (colb + 1 > r1) s[nt][3] = -1e30f;
                }
            }

            // online softmax
            {
                float mx0 = -1e30f, mx1 = -1e30f;
                #pragma unroll
                for (int nt = 0; nt < 8; nt++) {
                    mx0 = fmaxf(mx0, fmaxf(s[nt][0], s[nt][1]));
                    mx1 = fmaxf(mx1, fmaxf(s[nt][2], s[nt][3]));
                }
                mx0 = fmaxf(mx0, __shfl_xor_sync(0xffffffffu, mx0, 1));
                mx0 = fmaxf(mx0, __shfl_xor_sync(0xffffffffu, mx0, 2));
                mx1 = fmaxf(mx1, __shfl_xor_sync(0xffffffffu, mx1, 1));
                mx1 = fmaxf(mx1, __shfl_xor_sync(0xffffffffu, mx1, 2));

                const float mn0 = fmaxf(m0, mx0), mn1 = fmaxf(m1, mx1);
                const float a0 = __expf(m0 - mn0), a1 = __expf(m1 - mn1);
                float s0 = 0.f, s1 = 0.f;
                #pragma unroll
                for (int nt = 0; nt < 8; nt++) {
                    s[nt][0] = __expf(s[nt][0] - mn0);
                    s[nt][1] = __expf(s[nt][1] - mn0);
                    s[nt][2] = __expf(s[nt][2] - mn1);
                    s[nt][3] = __expf(s[nt][3] - mn1);
                    s0 += s[nt][0] + s[nt][1];
                    s1 += s[nt][2] + s[nt][3];
                }
                s0 += __shfl_xor_sync(0xffffffffu, s0, 1);
                s0 += __shfl_xor_sync(0xffffffffu, s0, 2);
                s1 += __shfl_xor_sync(0xffffffffu, s1, 1);
                s1 += __shfl_xor_sync(0xffffffffu, s1, 2);
                l0 = l0 * a0 + s0;  m0 = mn0;
                l1 = l1 * a1 + s1;  m1 = mn1;
                #pragma unroll
                for (int nt = 0; nt < 8; nt++) {
                    o[nt][0] *= a0; o[nt][1] *= a0;
                    o[nt][2] *= a1; o[nt][3] *= a1;
                }
            }

            // O += P V  (V read transposed via ldmatrix.trans)
            #pragma unroll
            for (int kc = 0; kc < 4; kc++) {
                uint32_t ph[4], pl[4];
                split2(s[2 * kc][0],     s[2 * kc][1],     ph[0], pl[0]);
                split2(s[2 * kc][2],     s[2 * kc][3],     ph[1], pl[1]);
                split2(s[2 * kc + 1][0], s[2 * kc + 1][1], ph[2], pl[2]);
                split2(s[2 * kc + 1][2], s[2 * kc + 1][3], ph[3], pl[3]);
                #pragma unroll
                for (int p = 0; p < 4; p++) {
                    const uint32_t voff = ((kc * 16 + vb_r) * AST + p * 16 + vb_c) * 2;
                    uint32_t bh4[4], bl4[4];
                    ldsm4t(bh4, uVhi + voff);
                    ldsm4t(bl4, uVlo + voff);
                    mma_bf16(o[2 * p],     ph, bh4);
                    mma_bf16(o[2 * p + 1], ph, bh4 + 2);
                    mma_bf16(o[2 * p],     ph, bl4);
                    mma_bf16(o[2 * p + 1], ph, bl4 + 2);
                    mma_bf16(o[2 * p],     pl, bh4);
                    mma_bf16(o[2 * p + 1], pl, bh4 + 2);
                }
            }
        }
        __syncthreads();
    }

    // normalize + split-store
    const float i0 = 1.f / l0, i1 = 1.f / l1;
    #pragma unroll
    for (int nt = 0; nt < 8; nt++) {
        const int col = h * D_SZ + nt * 8 + 2 * qk;
        const size_t r0 = seq0 + wr + qr, r1 = r0 + 8;
        uint32_t hh, ll;
        split2(o[nt][0] * i0, o[nt][1] * i0, hh, ll);
        *(uint32_t*)(ah + r0 * HD + col) = hh;
        *(uint32_t*)(al + r0 * HD + col) = ll;
        split2(o[nt][2] * i1, o[nt][3] * i1, hh, ll);
        *(uint32_t*)(ah + r1 * HD + col) = hh;
        *(uint32_t*)(al + r1 * HD + col) = ll;
    }
}

// ---------------------------------------------------------------------------
extern "C" void kernel_launch(void* const* d_in, const int* in_sizes, int n_in,
                              void* d_out, int out_size)
{
    const float* x     = (const float*)d_in[0];
    const float* w_qkv = (const float*)d_in[1];
    const float* w_out = (const float*)d_in[2];
    float* out = (float*)d_out;

    bf16 *xh, *xl, *wqh, *wql, *woh, *wol, *qh, *ql, *ahp, *alp;
    cudaGetSymbolAddress((void**)&xh,  g_xh);  cudaGetSymbolAddress((void**)&xl,  g_xl);
    cudaGetSymbolAddress((void**)&wqh, g_wqh); cudaGetSymbolAddress((void**)&wql, g_wql);
    cudaGetSymbolAddress((void**)&woh, g_woh); cudaGetSymbolAddress((void**)&wol, g_wol);
    cudaGetSymbolAddress((void**)&qh,  g_qh);  cudaGetSymbolAddress((void**)&ql,  g_ql);
    cudaGetSymbolAddress((void**)&ahp, g_ah);  cudaGetSymbolAddress((void**)&alp, g_al);

    cudaFuncSetAttribute(gemm_bf3_kernel<true>,
                         cudaFuncAttributeMaxDynamicSharedMemorySize, GEMM_SMEM);
    cudaFuncSetAttribute(gemm_bf3_kernel<false>,
                         cudaFuncAttributeMaxDynamicSharedMemorySize, GEMM_SMEM);

    // 0) split inputs once
    {
        int n4 = (M_SZ * E_SZ) / 4;
        split_kernel<<<(n4 + 255) / 256, 256>>>(x, xh, xl, n4);
        n4 = (F3 * E_SZ) / 4;
        split_kernel<<<(n4 + 255) / 256, 256>>>(w_qkv, wqh, wql, n4);
        n4 = (E_SZ * HD) / 4;
        split_kernel<<<(n4 + 255) / 256, 256>>>(w_out, woh, wol, n4);
    }

    // 1) QKV projection -> split bf16 qkv
    {
        dim3 grid(F3 / 128, M_SZ / 128);
        gemm_bf3_kernel<true><<<grid, 256, GEMM_SMEM>>>(
            xh, xl, wqh, wql, nullptr, qh, ql, M_SZ, F3, E_SZ);
    }

    // 2) causal flash attention -> split bf16 attn
    {
        dim3 grid(C_SZ / 128, B_SZ * H_SZ);
        attn_mma_kernel<<<grid, 256>>>(qh, ql, ahp, alp);
    }

    // 3) output projection -> fp32 out
    {
        dim3 grid(E_SZ / 128, M_SZ / 128);
        gemm_bf3_kernel<false><<<grid, 256, GEMM_SMEM>>>(
            ahp, alp, woh, wol, out, nullptr, nullptr, M_SZ, E_SZ, HD);
    }
}

// round 8
// speedup vs baseline: 3.8034x; 1.1481x over previous
#include <cuda_runtime.h>
#include <cuda_bf16.h>
#include <math.h>
#include <cstdint>

// Problem constants
#define B_SZ 4
#define C_SZ 2048
#define E_SZ 1024
#define H_SZ 16
#define D_SZ 64
#define HD   (H_SZ * D_SZ)     // 1024
#define F3   (3 * HD)          // 3072
#define M_SZ (B_SZ * C_SZ)     // 8192

typedef __nv_bfloat16 bf16;

// Pre-split scratch (bf16 hi/lo pairs)
__device__ bf16 g_xh[(size_t)M_SZ * E_SZ],  g_xl[(size_t)M_SZ * E_SZ];
__device__ bf16 g_wqh[(size_t)F3 * E_SZ],   g_wql[(size_t)F3 * E_SZ];
__device__ bf16 g_woh[(size_t)E_SZ * HD],   g_wol[(size_t)E_SZ * HD];
__device__ bf16 g_qh[(size_t)M_SZ * F3],    g_ql[(size_t)M_SZ * F3];
__device__ bf16 g_ah[(size_t)M_SZ * HD],    g_al[(size_t)M_SZ * HD];

// ---------------------------------------------------------------------------
// Helpers
// ---------------------------------------------------------------------------
__device__ __forceinline__ uint32_t smem_u32(const void* p) {
    uint32_t a;
    asm("{ .reg .u64 t; cvta.to.shared.u64 t, %1; cvt.u32.u64 %0, t; }"
        : "=r"(a) : "l"(p));
    return a;
}
#define CP_ASYNC16(dst, src) \
    asm volatile("cp.async.cg.shared.global [%0], [%1], 16;" \
        :: "r"(dst), "l"(src) : "memory")
#define CP_COMMIT() asm volatile("cp.async.commit_group;" ::: "memory")
#define CP_WAIT(n)  asm volatile("cp.async.wait_group %0;" :: "n"(n) : "memory")

__device__ __forceinline__ void mma_bf16(float* c, const uint32_t* a, const uint32_t* b) {
    asm volatile(
        "mma.sync.aligned.m16n8k16.row.col.f32.bf16.bf16.f32 "
        "{%0,%1,%2,%3}, {%4,%5,%6,%7}, {%8,%9}, {%0,%1,%2,%3};"
        : "+f"(c[0]), "+f"(c[1]), "+f"(c[2]), "+f"(c[3])
        : "r"(a[0]), "r"(a[1]), "r"(a[2]), "r"(a[3]), "r"(b[0]), "r"(b[1]));
}

__device__ __forceinline__ void ldsm4(uint32_t* r, uint32_t addr) {
    asm volatile("ldmatrix.sync.aligned.m8n8.x4.shared.b16 {%0,%1,%2,%3}, [%4];"
        : "=r"(r[0]), "=r"(r[1]), "=r"(r[2]), "=r"(r[3]) : "r"(addr));
}
__device__ __forceinline__ void ldsm4t(uint32_t* r, uint32_t addr) {
    asm volatile("ldmatrix.sync.aligned.m8n8.x4.trans.shared.b16 {%0,%1,%2,%3}, [%4];"
        : "=r"(r[0]), "=r"(r[1]), "=r"(r[2]), "=r"(r[3]) : "r"(addr));
}

__device__ __forceinline__ uint32_t pack_bf16(bf16 a, bf16 b) {
    uint16_t lo = __bfloat16_as_ushort(a), hi = __bfloat16_as_ushort(b);
    return ((uint32_t)hi << 16) | lo;
}
__device__ __forceinline__ void split2(float x, float y, uint32_t& hi, uint32_t& lo) {
    bf16 hx = __float2bfloat16(x), hy = __float2bfloat16(y);
    bf16 lx = __float2bfloat16(x - __bfloat162float(hx));
    bf16 ly = __float2bfloat16(y - __bfloat162float(hy));
    hi = pack_bf16(hx, hy);
    lo = pack_bf16(lx, ly);
}

// ---------------------------------------------------------------------------
// Elementwise fp32 -> (hi, lo) bf16 split
// ---------------------------------------------------------------------------
__global__ __launch_bounds__(256) void split_kernel(
    const float* __restrict__ in, bf16* __restrict__ hi, bf16* __restrict__ lo, int n4)
{
    int i = blockIdx.x * 256 + threadIdx.x;
    if (i >= n4) return;
    float4 v = *(const float4*)(in + (size_t)i * 4);
    uint32_t h0, l0, h1, l1;
    split2(v.x, v.y, h0, l0);
    split2(v.z, v.w, h1, l1);
    *(uint2*)(hi + (size_t)i * 4) = make_uint2(h0, h1);
    *(uint2*)(lo + (size_t)i * 4) = make_uint2(l0, l1);
}

// ---------------------------------------------------------------------------
// Pure split-bf16 GEMM with ldmatrix (unchanged from R7)
// ---------------------------------------------------------------------------
#define SSTB 40
#define OPB (128 * SSTB)
#define BUFB (4 * OPB)
#define GEMM_SMEM (2 * BUFB * 2)

template <bool SPLIT_OUT>
__global__ __launch_bounds__(256, 2) void gemm_bf3_kernel(
    const bf16* __restrict__ Ahi_g, const bf16* __restrict__ Alo_g,
    const bf16* __restrict__ Bhi_g, const bf16* __restrict__ Blo_g,
    float* __restrict__ Cf, bf16* __restrict__ Chi, bf16* __restrict__ Clo,
    int M, int N, int K)
{
    extern __shared__ bf16 sm[];
    const uint32_t smb = smem_u32(sm);

    const int tid  = threadIdx.x;
    const int wid  = tid >> 5, lane = tid & 31;
    const int bm   = blockIdx.y * 128, bn = blockIdx.x * 128;
    const int wm   = (wid & 3) * 32;
    const int wn   = (wid >> 2) * 64;
    const int qr   = lane >> 2;
    const int qk   = lane & 3;

    const int t8 = lane >> 3, r8 = lane & 7;
    const int a_r = ((t8 & 1) << 3) + r8;
    const int a_c = (t8 >> 1) << 3;
    const int b_r = ((t8 >> 1) << 3) + r8;
    const int b_c = (t8 & 1) << 3;

    const int lr0 = tid >> 2;
    const int lq  = tid & 3;

    const bf16* gAh0 = Ahi_g + (size_t)(bm + lr0) * K + lq * 8;
    const bf16* gAl0 = Alo_g + (size_t)(bm + lr0) * K + lq * 8;
    const bf16* gBh0 = Bhi_g + (size_t)(bn + lr0) * K + lq * 8;
    const bf16* gBl0 = Blo_g + (size_t)(bn + lr0) * K + lq * 8;
    const size_t rstep = (size_t)64 * K;

    uint32_t sAh[2], sAl[2], sBh[2], sBl[2];
    #pragma unroll
    for (int b = 0; b < 2; b++) {
        const uint32_t base = smb + b * BUFB * 2;
        sAh[b] = base + (lr0 * SSTB + lq * 8) * 2;
        sAl[b] = sAh[b] + OPB * 2;
        sBh[b] = sAl[b] + OPB * 2;
        sBl[b] = sBh[b] + OPB * 2;
    }
    const uint32_t sstep = 64 * SSTB * 2;

    float acc[2][8][4];
    #pragma unroll
    for (int mt = 0; mt < 2; mt++)
        #pragma unroll
        for (int nt = 0; nt < 8; nt++)
            #pragma unroll
            for (int v = 0; v < 4; v++) acc[mt][nt][v] = 0.f;

    const int NT = K / 32;

    CP_ASYNC16(sAh[0], gAh0);  CP_ASYNC16(sAh[0] + sstep, gAh0 + rstep);
    CP_ASYNC16(sAl[0], gAl0);  CP_ASYNC16(sAl[0] + sstep, gAl0 + rstep);
    CP_ASYNC16(sBh[0], gBh0);  CP_ASYNC16(sBh[0] + sstep, gBh0 + rstep);
    CP_ASYNC16(sBl[0], gBl0);  CP_ASYNC16(sBl[0] + sstep, gBl0 + rstep);
    CP_COMMIT();

    for (int kt = 0; kt < NT; kt++) {
        const int buf = kt & 1;
        if (kt + 1 < NT) {
            const int nb = buf ^ 1;
            const int off = (kt + 1) * 32;
            CP_ASYNC16(sAh[nb], gAh0 + off);  CP_ASYNC16(sAh[nb] + sstep, gAh0 + rstep + off);
            CP_ASYNC16(sAl[nb], gAl0 + off);  CP_ASYNC16(sAl[nb] + sstep, gAl0 + rstep + off);
            CP_ASYNC16(sBh[nb], gBh0 + off);  CP_ASYNC16(sBh[nb] + sstep, gBh0 + rstep + off);
            CP_ASYNC16(sBl[nb], gBl0 + off);  CP_ASYNC16(sBl[nb] + sstep, gBl0 + rstep + off);
            CP_COMMIT();
            CP_WAIT(1);
        } else {
            CP_WAIT(0);
        }
        __syncthreads();

        const uint32_t bAh = smb + buf * BUFB * 2;
        const uint32_t bAl = bAh + OPB * 2;
        const uint32_t bBh = bAl + OPB * 2;
        const uint32_t bBl = bBh + OPB * 2;

        #pragma unroll
        for (int ks = 0; ks < 2; ks++) {
            const int k0 = ks * 16;
            uint32_t afh[2][4], afl[2][4];
            #pragma unroll
            for (int mt = 0; mt < 2; mt++) {
                const uint32_t aoff = ((wm + mt * 16 + a_r) * SSTB + k0 + a_c) * 2;
                ldsm4(afh[mt], bAh + aoff);
                ldsm4(afl[mt], bAl + aoff);
            }
            #pragma unroll
            for (int p = 0; p < 4; p++) {
                const uint32_t boff = ((wn + p * 16 + b_r) * SSTB + k0 + b_c) * 2;
                uint32_t bh4[4], bl4[4];
                ldsm4(bh4, bBh + boff);
                ldsm4(bl4, bBl + boff);
                #pragma unroll
                for (int mt = 0; mt < 2; mt++) {
                    mma_bf16(acc[mt][2 * p],     afh[mt], bh4);
                    mma_bf16(acc[mt][2 * p + 1], afh[mt], bh4 + 2);
                }
                #pragma unroll
                for (int mt = 0; mt < 2; mt++) {
                    mma_bf16(acc[mt][2 * p],     afh[mt], bl4);
                    mma_bf16(acc[mt][2 * p + 1], afh[mt], bl4 + 2);
                }
                #pragma unroll
                for (int mt = 0; mt < 2; mt++) {
                    mma_bf16(acc[mt][2 * p],     afl[mt], bh4);
                    mma_bf16(acc[mt][2 * p + 1], afl[mt], bh4 + 2);
                }
            }
        }
        __syncthreads();
    }

    #pragma unroll
    for (int mt = 0; mt < 2; mt++) {
        const int r = bm + wm + mt * 16 + qr;
        #pragma unroll
        for (int nt = 0; nt < 8; nt++) {
            const int ncol = bn + wn + nt * 8 + 2 * qk;
            if (SPLIT_OUT) {
                uint32_t h, l;
                split2(acc[mt][nt][0], acc[mt][nt][1], h, l);
                *(uint32_t*)(Chi + (size_t)r * N + ncol) = h;
                *(uint32_t*)(Clo + (size_t)r * N + ncol) = l;
                split2(acc[mt][nt][2], acc[mt][nt][3], h, l);
                *(uint32_t*)(Chi + (size_t)(r + 8) * N + ncol) = h;
                *(uint32_t*)(Clo + (size_t)(r + 8) * N + ncol) = l;
            } else {
                *(float2*)(Cf + (size_t)r * N + ncol) =
                    make_float2(acc[mt][nt][0], acc[mt][nt][1]);
                *(float2*)(Cf + (size_t)(r + 8) * N + ncol) =
                    make_float2(acc[mt][nt][2], acc[mt][nt][3]);
            }
        }
    }
}

// ---------------------------------------------------------------------------
// Flash attention, double-buffered K/V stages, one barrier per kv tile.
// grid = (B*H, C/128); qb reversed for LPT scheduling.
// ---------------------------------------------------------------------------
#define AST 72
#define ATILE (64 * AST)                 // bf16 units per operand tile (4608)
#define ASTAGE (4 * ATILE)               // Khi,Klo,Vhi,Vlo per stage
#define ATTN_SMEM (2 * ASTAGE * 2)       // bytes: 73728

__global__ __launch_bounds__(256) void attn_mma_kernel(
    const bf16* __restrict__ qh, const bf16* __restrict__ ql,
    bf16* __restrict__ ah, bf16* __restrict__ al)
{
    extern __shared__ bf16 asmem[];
    const uint32_t smb = smem_u32(asmem);

    const int tid = threadIdx.x, wid = tid >> 5, lane = tid & 31;
    const int qr = lane >> 2, qk = lane & 3;
    const int qb = (int)gridDim.y - 1 - (int)blockIdx.y;   // reversed: big work first
    const int bh = blockIdx.x;
    const int b = bh >> 4, h = bh & 15;

    const size_t seq0 = (size_t)b * C_SZ;
    const int wr = qb * 128 + wid * 16;

    // ldmatrix lane geometry
    const int t8 = lane >> 3, r8 = lane & 7;
    const int kb_r = ((t8 >> 1) << 3) + r8;
    const int kb_c = (t8 & 1) << 3;
    const int vb_r = ((t8 & 1) << 3) + r8;
    const int vb_c = (t8 >> 1) << 3;

    // loader mapping: row = tid>>3 (0..31, +32), 16B chunk = tid&7
    const int kr0 = tid >> 3;
    const int kq  = tid & 7;
    const uint32_t lsoff = (kr0 * AST + kq * 8) * 2;
    const uint32_t kstep = 32 * AST * 2;

    // Q fragments
    uint32_t qhi[4][4], qlo[4][4];
    {
        const bf16* qb0 = qh + (seq0 + wr) * F3 + h * D_SZ;
        const bf16* qb1 = ql + (seq0 + wr) * F3 + h * D_SZ;
        #pragma unroll
        for (int kc = 0; kc < 4; kc++) {
            const int d0 = kc * 16 + 2 * qk;
            qhi[kc][0] = *(const uint32_t*)(qb0 + (size_t)qr * F3 + d0);
            qhi[kc][1] = *(const uint32_t*)(qb0 + (size_t)(qr + 8) * F3 + d0);
            qhi[kc][2] = *(const uint32_t*)(qb0 + (size_t)qr * F3 + d0 + 8);
            qhi[kc][3] = *(const uint32_t*)(qb0 + (size_t)(qr + 8) * F3 + d0 + 8);
            qlo[kc][0] = *(const uint32_t*)(qb1 + (size_t)qr * F3 + d0);
            qlo[kc][1] = *(const uint32_t*)(qb1 + (size_t)(qr + 8) * F3 + d0);
            qlo[kc][2] = *(const uint32_t*)(qb1 + (size_t)qr * F3 + d0 + 8);
            qlo[kc][3] = *(const uint32_t*)(qb1 + (size_t)(qr + 8) * F3 + d0 + 8);
        }
    }

    float m0 = -1e30f, m1 = -1e30f, l0 = 0.f, l1 = 0.f;
    float o[8][4];
    #pragma unroll
    for (int nt = 0; nt < 8; nt++)
        #pragma unroll
        for (int v = 0; v < 4; v++) o[nt][v] = 0.f;

    const int nkv = 2 * qb + 2;

    // stage loader: issue all K/V cp.async for tile kb into stage s
    auto issue_tile = [&](int kb, int s) {
        const uint32_t sb = smb + s * ASTAGE * 2;
        const uint32_t uKh = sb,                 uKl = sb + ATILE * 2;
        const uint32_t uVh = sb + 2 * ATILE * 2, uVl = sb + 3 * ATILE * 2;
        const size_t krow0 = (seq0 + kb * 64 + kr0) * F3;
        const size_t kr32 = (size_t)32 * F3;
        const bf16* gKh = qh + krow0 + HD + h * D_SZ + kq * 8;
        const bf16* gKl = ql + krow0 + HD + h * D_SZ + kq * 8;
        const bf16* gVh = qh + krow0 + 2 * HD + h * D_SZ + kq * 8;
        const bf16* gVl = ql + krow0 + 2 * HD + h * D_SZ + kq * 8;
        CP_ASYNC16(uKh + lsoff, gKh);  CP_ASYNC16(uKh + lsoff + kstep, gKh + kr32);
        CP_ASYNC16(uKl + lsoff, gKl);  CP_ASYNC16(uKl + lsoff + kstep, gKl + kr32);
        CP_ASYNC16(uVh + lsoff, gVh);  CP_ASYNC16(uVh + lsoff + kstep, gVh + kr32);
        CP_ASYNC16(uVl + lsoff, gVl);  CP_ASYNC16(uVl + lsoff + kstep, gVl + kr32);
        CP_COMMIT();
    };

    issue_tile(0, 0);

    for (int kb = 0; kb < nkv; kb++) {
        CP_WAIT(0);
        __syncthreads();   // publishes tile kb; also guards stage (kb+1)&1 overwrite

        if (kb + 1 < nkv) issue_tile(kb + 1, (kb + 1) & 1);

        if (kb * 64 <= wr + 15) {
            const uint32_t sb = smb + (kb & 1) * ASTAGE * 2;
            const uint32_t uKhi = sb,                 uKlo = sb + ATILE * 2;
            const uint32_t uVhi = sb + 2 * ATILE * 2, uVlo = sb + 3 * ATILE * 2;

            // S = Q K^T
            float s[8][4];
            #pragma unroll
            for (int nt = 0; nt < 8; nt++)
                #pragma unroll
                for (int v = 0; v < 4; v++) s[nt][v] = 0.f;

            #pragma unroll
            for (int kc = 0; kc < 4; kc++) {
                const int k0 = kc * 16;
                #pragma unroll
                for (int p = 0; p < 4; p++) {
                    const uint32_t boff = ((p * 16 + kb_r) * AST + k0 + kb_c) * 2;
                    uint32_t bh4[4], bl4[4];
                    ldsm4(bh4, uKhi + boff);
                    ldsm4(bl4, uKlo + boff);
                    mma_bf16(s[2 * p],     qhi[kc], bh4);
                    mma_bf16(s[2 * p + 1], qhi[kc], bh4 + 2);
                    mma_bf16(s[2 * p],     qhi[kc], bl4);
                    mma_bf16(s[2 * p + 1], qhi[kc], bl4 + 2);
                    mma_bf16(s[2 * p],     qlo[kc], bh4);
                    mma_bf16(s[2 * p + 1], qlo[kc], bh4 + 2);
                }
            }

            // scale + causal mask
            const bool edge = (kb * 64 + 63 > wr);
            #pragma unroll
            for (int nt = 0; nt < 8; nt++) {
                #pragma unroll
                for (int v = 0; v < 4; v++) s[nt][v] *= 0.125f;
                if (edge) {
                    const int colb = kb * 64 + nt * 8 + 2 * qk;
                    const int r0 = wr + qr, r1 = r0 + 8;
                    if (colb > r0)     s[nt][0] = -1e30f;
                    if (colb + 1 > r0) s[nt][1] = -1e30f;
                    if (colb > r1)     s[nt][2] = -1e30f;
                    if (colb + 1 > r1) s[nt][3] = -1e30f;
                }
            }

            // online softmax
            {
                float mx0 = -1e30f, mx1 = -1e30f;
                #pragma unroll
                for (int nt = 0; nt < 8; nt++) {
                    mx0 = fmaxf(mx0, fmaxf(s[nt][0], s[nt][1]));
                    mx1 = fmaxf(mx1, fmaxf(s[nt][2], s[nt][3]));
                }
                mx0 = fmaxf(mx0, __shfl_xor_sync(0xffffffffu, mx0, 1));
                mx0 = fmaxf(mx0, __shfl_xor_sync(0xffffffffu, mx0, 2));
                mx1 = fmaxf(mx1, __shfl_xor_sync(0xffffffffu, mx1, 1));
                mx1 = fmaxf(mx1, __shfl_xor_sync(0xffffffffu, mx1, 2));

                const float mn0 = fmaxf(m0, mx0), mn1 = fmaxf(m1, mx1);
                const float a0 = __expf(m0 - mn0), a1 = __expf(m1 - mn1);
                float s0 = 0.f, s1 = 0.f;
                #pragma unroll
                for (int nt = 0; nt < 8; nt++) {
                    s[nt][0] = __expf(s[nt][0] - mn0);
                    s[nt][1] = __expf(s[nt][1] - mn0);
                    s[nt][2] = __expf(s[nt][2] - mn1);
                    s[nt][3] = __expf(s[nt][3] - mn1);
                    s0 += s[nt][0] + s[nt][1];
                    s1 += s[nt][2] + s[nt][3];
                }
                s0 += __shfl_xor_sync(0xffffffffu, s0, 1);
                s0 += __shfl_xor_sync(0xffffffffu, s0, 2);
                s1 += __shfl_xor_sync(0xffffffffu, s1, 1);
                s1 += __shfl_xor_sync(0xffffffffu, s1, 2);
                l0 = l0 * a0 + s0;  m0 = mn0;
                l1 = l1 * a1 + s1;  m1 = mn1;
                #pragma unroll
                for (int nt = 0; nt < 8; nt++) {
                    o[nt][0] *= a0; o[nt][1] *= a0;
                    o[nt][2] *= a1; o[nt][3] *= a1;
                }
            }

            // O += P V
            #pragma unroll
            for (int kc = 0; kc < 4; kc++) {
                uint32_t ph[4], pl[4];
                split2(s[2 * kc][0],     s[2 * kc][1],     ph[0], pl[0]);
                split2(s[2 * kc][2],     s[2 * kc][3],     ph[1], pl[1]);
                split2(s[2 * kc + 1][0], s[2 * kc + 1][1], ph[2], pl[2]);
                split2(s[2 * kc + 1][2], s[2 * kc + 1][3], ph[3], pl[3]);
                #pragma unroll
                for (int p = 0; p < 4; p++) {
                    const uint32_t voff = ((kc * 16 + vb_r) * AST + p * 16 + vb_c) * 2;
                    uint32_t bh4[4], bl4[4];
                    ldsm4t(bh4, uVhi + voff);
                    ldsm4t(bl4, uVlo + voff);
                    mma_bf16(o[2 * p],     ph, bh4);
                    mma_bf16(o[2 * p + 1], ph, bh4 + 2);
                    mma_bf16(o[2 * p],     ph, bl4);
                    mma_bf16(o[2 * p + 1], ph, bl4 + 2);
                    mma_bf16(o[2 * p],     pl, bh4);
                    mma_bf16(o[2 * p + 1], pl, bh4 + 2);
                }
            }
        }
    }

    // normalize + split-store
    const float i0 = 1.f / l0, i1 = 1.f / l1;
    #pragma unroll
    for (int nt = 0; nt < 8; nt++) {
        const int col = h * D_SZ + nt * 8 + 2 * qk;
        const size_t r0 = seq0 + wr + qr, r1 = r0 + 8;
        uint32_t hh, ll;
        split2(o[nt][0] * i0, o[nt][1] * i0, hh, ll);
        *(uint32_t*)(ah + r0 * HD + col) = hh;
        *(uint32_t*)(al + r0 * HD + col) = ll;
        split2(o[nt][2] * i1, o[nt][3] * i1, hh, ll);
        *(uint32_t*)(ah + r1 * HD + col) = hh;
        *(uint32_t*)(al + r1 * HD + col) = ll;
    }
}

// ---------------------------------------------------------------------------
extern "C" void kernel_launch(void* const* d_in, const int* in_sizes, int n_in,
                              void* d_out, int out_size)
{
    const float* x     = (const float*)d_in[0];
    const float* w_qkv = (const float*)d_in[1];
    const float* w_out = (const float*)d_in[2];
    float* out = (float*)d_out;

    bf16 *xh, *xl, *wqh, *wql, *woh, *wol, *qh, *ql, *ahp, *alp;
    cudaGetSymbolAddress((void**)&xh,  g_xh);  cudaGetSymbolAddress((void**)&xl,  g_xl);
    cudaGetSymbolAddress((void**)&wqh, g_wqh); cudaGetSymbolAddress((void**)&wql, g_wql);
    cudaGetSymbolAddress((void**)&woh, g_woh); cudaGetSymbolAddress((void**)&wol, g_wol);
    cudaGetSymbolAddress((void**)&qh,  g_qh);  cudaGetSymbolAddress((void**)&ql,  g_ql);
    cudaGetSymbolAddress((void**)&ahp, g_ah);  cudaGetSymbolAddress((void**)&alp, g_al);

    cudaFuncSetAttribute(gemm_bf3_kernel<true>,
                         cudaFuncAttributeMaxDynamicSharedMemorySize, GEMM_SMEM);
    cudaFuncSetAttribute(gemm_bf3_kernel<false>,
                         cudaFuncAttributeMaxDynamicSharedMemorySize, GEMM_SMEM);
    cudaFuncSetAttribute(attn_mma_kernel,
                         cudaFuncAttributeMaxDynamicSharedMemorySize, ATTN_SMEM);

    // 0) split inputs once
    {
        int n4 = (M_SZ * E_SZ) / 4;
        split_kernel<<<(n4 + 255) / 256, 256>>>(x, xh, xl, n4);
        n4 = (F3 * E_SZ) / 4;
        split_kernel<<<(n4 + 255) / 256, 256>>>(w_qkv, wqh, wql, n4);
        n4 = (E_SZ * HD) / 4;
        split_kernel<<<(n4 + 255) / 256, 256>>>(w_out, woh, wol, n4);
    }

    // 1) QKV projection -> split bf16 qkv
    {
        dim3 grid(F3 / 128, M_SZ / 128);
        gemm_bf3_kernel<true><<<grid, 256, GEMM_SMEM>>>(
            xh, xl, wqh, wql, nullptr, qh, ql, M_SZ, F3, E_SZ);
    }

    // 2) causal flash attention -> split bf16 attn (qb reversed inside)
    {
        dim3 grid(B_SZ * H_SZ, C_SZ / 128);
        attn_mma_kernel<<<grid, 256, ATTN_SMEM>>>(qh, ql, ahp, alp);
    }

    // 3) output projection -> fp32 out
    {
        dim3 grid(E_SZ / 128, M_SZ / 128);
        gemm_bf3_kernel<false><<<grid, 256, GEMM_SMEM>>>(
            ahp, alp, woh, wol, out, nullptr, nullptr, M_SZ, E_SZ, HD);
    }
}